// round 1
// baseline (speedup 1.0000x reference)
#include <cuda_runtime.h>
#include <math.h>

// ---------------------------------------------------------------------------
// Problem constants
// ---------------------------------------------------------------------------
#define BATCH     2
#define SEQ       2048
#define DMODEL    4096
#define NHEADS    32
#define KVHEADS   8
#define HEADDIM   128
#define QKV_N     (DMODEL + 2 * KVHEADS * HEADDIM)   // 6144
#define TOKENS    (BATCH * SEQ)                      // 4096
#define CLIP_V    8.0f
#define INV_SQRT_D 0.08838834764831845f              // 1/sqrt(128)

// ---------------------------------------------------------------------------
// Scratch (device globals; no dynamic allocation allowed)
// ---------------------------------------------------------------------------
__device__ float g_qkv [(size_t)TOKENS * QKV_N];                    // [b,s,6144]
__device__ float g_qt  [(size_t)BATCH * NHEADS  * HEADDIM * SEQ];   // [b,h,d,s], pre-scaled
__device__ float g_kt  [(size_t)BATCH * KVHEADS * HEADDIM * SEQ];   // [b,hk,d,s]
__device__ float g_attn[(size_t)TOKENS * DMODEL];                   // [b,s,4096]

// ---------------------------------------------------------------------------
// SGEMM:  C[M,N] = A[M,K] * B[N,K]^T   (both row-major, K contiguous)
// 128x128 tile, BK=8, 256 threads, 8x8 per-thread, double buffered.
// ---------------------------------------------------------------------------
template <bool DO_CLIP>
__global__ __launch_bounds__(256)
void sgemm_nt(const float* __restrict__ A, const float* __restrict__ B,
              float* __restrict__ C, int M, int N, int K)
{
    __shared__ float As[2][8][128];
    __shared__ float Bs[2][8][128];

    const int tid  = threadIdx.x;
    const int tr   = tid >> 4;        // 0..15  (row group, 8 rows each)
    const int tc   = tid & 15;        // 0..15  (col group, 8 cols each)
    const int lrow = tid >> 1;        // 0..127 (load row)
    const int lc4  = (tid & 1) << 2;  // 0 or 4 (load col4)

    const int m0 = blockIdx.y * 128;
    const int n0 = blockIdx.x * 128;

    const float* Ag = A + (size_t)(m0 + lrow) * K + lc4;
    const float* Bg = B + (size_t)(n0 + lrow) * K + lc4;

    {   // stage 0
        float4 a = *(const float4*)Ag;
        float4 b = *(const float4*)Bg;
        As[0][lc4+0][lrow] = a.x; As[0][lc4+1][lrow] = a.y;
        As[0][lc4+2][lrow] = a.z; As[0][lc4+3][lrow] = a.w;
        Bs[0][lc4+0][lrow] = b.x; Bs[0][lc4+1][lrow] = b.y;
        Bs[0][lc4+2][lrow] = b.z; Bs[0][lc4+3][lrow] = b.w;
    }
    __syncthreads();

    float acc[8][8];
    #pragma unroll
    for (int i = 0; i < 8; i++)
        #pragma unroll
        for (int j = 0; j < 8; j++) acc[i][j] = 0.0f;

    const int nk = K >> 3;
    int buf = 0;
    for (int kt = 0; kt < nk; kt++) {
        float4 na, nb;
        const bool has_next = (kt + 1 < nk);
        if (has_next) {
            na = *(const float4*)(Ag + (kt + 1) * 8);
            nb = *(const float4*)(Bg + (kt + 1) * 8);
        }
        #pragma unroll
        for (int k = 0; k < 8; k++) {
            float ar[8], br[8];
            *(float4*)&ar[0] = *(const float4*)&As[buf][k][tr * 8];
            *(float4*)&ar[4] = *(const float4*)&As[buf][k][tr * 8 + 4];
            *(float4*)&br[0] = *(const float4*)&Bs[buf][k][tc * 8];
            *(float4*)&br[4] = *(const float4*)&Bs[buf][k][tc * 8 + 4];
            #pragma unroll
            for (int i = 0; i < 8; i++)
                #pragma unroll
                for (int j = 0; j < 8; j++)
                    acc[i][j] += ar[i] * br[j];
        }
        if (has_next) {
            const int nbuf = buf ^ 1;
            As[nbuf][lc4+0][lrow] = na.x; As[nbuf][lc4+1][lrow] = na.y;
            As[nbuf][lc4+2][lrow] = na.z; As[nbuf][lc4+3][lrow] = na.w;
            Bs[nbuf][lc4+0][lrow] = nb.x; Bs[nbuf][lc4+1][lrow] = nb.y;
            Bs[nbuf][lc4+2][lrow] = nb.z; Bs[nbuf][lc4+3][lrow] = nb.w;
        }
        __syncthreads();
        buf ^= 1;
    }

    float* Cp = C + (size_t)(m0 + tr * 8) * N + n0 + tc * 8;
    #pragma unroll
    for (int i = 0; i < 8; i++) {
        #pragma unroll
        for (int j4 = 0; j4 < 8; j4 += 4) {
            float4 v;
            v.x = acc[i][j4 + 0]; v.y = acc[i][j4 + 1];
            v.z = acc[i][j4 + 2]; v.w = acc[i][j4 + 3];
            if (DO_CLIP) {
                v.x = fminf(fmaxf(v.x, -CLIP_V), CLIP_V);
                v.y = fminf(fmaxf(v.y, -CLIP_V), CLIP_V);
                v.z = fminf(fmaxf(v.z, -CLIP_V), CLIP_V);
                v.w = fminf(fmaxf(v.w, -CLIP_V), CLIP_V);
            }
            *(float4*)(Cp + (size_t)i * N + j4) = v;
        }
    }
}

// ---------------------------------------------------------------------------
// RoPE + transpose: reads g_qkv rows, applies rotation (and 1/sqrt(d) to Q),
// scatters into d-major layouts g_qt[b,h,d,s] / g_kt[b,hk,d,s].
// position_ids is provably arange(S) broadcast -> use s directly.
// ---------------------------------------------------------------------------
__global__ __launch_bounds__(256)
void rope_kernel()
{
    const int token = blockIdx.x;          // 0..4095
    const int b    = token / SEQ;
    const int spos = token - b * SEQ;
    const float* row = g_qkv + (size_t)token * QKV_N;
    const float posf = (float)spos;

    for (int idx = threadIdx.x; idx < (NHEADS + KVHEADS) * 64; idx += 256) {
        const int h = idx >> 6;            // 0..39 (0..31 = Q heads, 32..39 = K heads)
        const int j = idx & 63;            // rotation pair index
        const float freq = powf(500000.0f, -(float)j * (1.0f / 64.0f));
        float s, c;
        sincosf(posf * freq, &s, &c);

        const float x1 = row[h * HEADDIM + j];
        const float x2 = row[h * HEADDIM + 64 + j];
        const float y1 = x1 * c - x2 * s;
        const float y2 = x2 * c + x1 * s;

        if (h < NHEADS) {
            float* q = g_qt + ((size_t)(b * NHEADS + h) * HEADDIM) * SEQ;
            q[(size_t)j * SEQ + spos]        = y1 * INV_SQRT_D;
            q[(size_t)(j + 64) * SEQ + spos] = y2 * INV_SQRT_D;
        } else {
            float* k = g_kt + ((size_t)(b * KVHEADS + (h - NHEADS)) * HEADDIM) * SEQ;
            k[(size_t)j * SEQ + spos]        = y1;
            k[(size_t)(j + 64) * SEQ + spos] = y2;
        }
    }
}

// ---------------------------------------------------------------------------
// Fused causal flash attention, fp32.
// Block: one (batch, head, 64-query tile). 256 threads as 16x16.
// Q,K read d-major (conflict-free smem GEMM without transposes),
// V read straight from g_qkv. Online softmax, causal tile skipping.
// smem: Qt[128][64] Kt[128][64] Vs[64][128] Ps[64][65]  = 114,944 B
// ---------------------------------------------------------------------------
#define ATTN_SMEM_FLOATS (8192 + 8192 + 8192 + 64 * 65)
#define ATTN_SMEM_BYTES  (ATTN_SMEM_FLOATS * 4)

__global__ __launch_bounds__(256, 2)
void attn_kernel()
{
    extern __shared__ float sm[];
    float* Qt = sm;               // [d][m]  d-major
    float* Kt = sm + 8192;        // [d][n]
    float* Vs = sm + 16384;       // [n][d]
    float* Ps = sm + 24576;       // [m][n]  row pitch 65

    const int qt = blockIdx.x;    // query tile (0..31)
    const int h  = blockIdx.y;    // head
    const int b  = blockIdx.z;    // batch
    const int hk = h >> 2;        // GQA: 4 q-heads share one kv-head
    const int q0 = qt * 64;

    const int tid = threadIdx.x;
    const int ty  = tid >> 4;     // 0..15 -> rows ty*4..+3
    const int tx  = tid & 15;     // 0..15 -> cols tx*4..+3 (A) / tx*8..+7 (C)

    const float* Qg = g_qt + ((size_t)(b * NHEADS + h) * HEADDIM) * SEQ + q0;
    const float* Kg = g_kt + ((size_t)(b * KVHEADS + hk) * HEADDIM) * SEQ;
    const float* Vg = g_qkv + (size_t)b * SEQ * QKV_N + DMODEL + KVHEADS * HEADDIM + hk * HEADDIM;

    // load Q tile (already scaled by 1/sqrt(d))
    for (int i = tid; i < 2048; i += 256) {
        const int d  = i >> 4;
        const int m4 = (i & 15) << 2;
        *(float4*)&Qt[d * 64 + m4] = *(const float4*)&Qg[(size_t)d * SEQ + m4];
    }

    float m_i[4], l_i[4], o[4][8];
    #pragma unroll
    for (int i = 0; i < 4; i++) {
        m_i[i] = -3.0e38f; l_i[i] = 0.0f;
        #pragma unroll
        for (int k = 0; k < 8; k++) o[i][k] = 0.0f;
    }

    for (int jt = 0; jt <= qt; jt++) {
        const int j0 = jt * 64;
        __syncthreads();   // prev iteration's phase C done with Vs/Ps

        for (int i = tid; i < 2048; i += 256) {           // K tile (d-major)
            const int d  = i >> 4;
            const int m4 = (i & 15) << 2;
            *(float4*)&Kt[d * 64 + m4] = *(const float4*)&Kg[(size_t)d * SEQ + j0 + m4];
        }
        for (int i = tid; i < 2048; i += 256) {           // V tile (s-major)
            const int j  = i >> 5;
            const int d4 = (i & 31) << 2;
            *(float4*)&Vs[j * 128 + d4] = *(const float4*)&Vg[(size_t)(j0 + j) * QKV_N + d4];
        }
        __syncthreads();

        // ---- phase A: S = Q K^T (scaled) ----
        float sacc[4][4];
        #pragma unroll
        for (int i = 0; i < 4; i++)
            #pragma unroll
            for (int j = 0; j < 4; j++) sacc[i][j] = 0.0f;

        #pragma unroll 4
        for (int d = 0; d < 128; d++) {
            const float4 a = *(const float4*)&Qt[d * 64 + ty * 4];
            const float4 v = *(const float4*)&Kt[d * 64 + tx * 4];
            const float av[4] = {a.x, a.y, a.z, a.w};
            const float bv[4] = {v.x, v.y, v.z, v.w};
            #pragma unroll
            for (int i = 0; i < 4; i++)
                #pragma unroll
                for (int j = 0; j < 4; j++)
                    sacc[i][j] += av[i] * bv[j];
        }

        if (jt == qt) {  // diagonal tile: causal mask
            #pragma unroll
            for (int i = 0; i < 4; i++)
                #pragma unroll
                for (int j = 0; j < 4; j++)
                    if (tx * 4 + j > ty * 4 + i) sacc[i][j] = -3.0e38f;
        }

        // ---- online softmax (rows distributed over 16 tx lanes) ----
        #pragma unroll
        for (int i = 0; i < 4; i++) {
            float tm = fmaxf(fmaxf(sacc[i][0], sacc[i][1]),
                             fmaxf(sacc[i][2], sacc[i][3]));
            #pragma unroll
            for (int off = 8; off >= 1; off >>= 1)
                tm = fmaxf(tm, __shfl_xor_sync(0xffffffffu, tm, off));
            const float mnew  = fmaxf(m_i[i], tm);
            const float alpha = __expf(m_i[i] - mnew);
            float rs = 0.0f;
            #pragma unroll
            for (int j = 0; j < 4; j++) {
                sacc[i][j] = __expf(sacc[i][j] - mnew);
                rs += sacc[i][j];
            }
            #pragma unroll
            for (int off = 8; off >= 1; off >>= 1)
                rs += __shfl_xor_sync(0xffffffffu, rs, off);
            l_i[i] = l_i[i] * alpha + rs;
            m_i[i] = mnew;
            #pragma unroll
            for (int k = 0; k < 8; k++) o[i][k] *= alpha;
            #pragma unroll
            for (int j = 0; j < 4; j++)
                Ps[(ty * 4 + i) * 65 + tx * 4 + j] = sacc[i][j];
        }
        __syncthreads();  // Ps visible to everyone

        // ---- phase C: O += P V ----
        #pragma unroll 2
        for (int j = 0; j < 64; j++) {
            const float aa[4] = {Ps[(ty * 4 + 0) * 65 + j],
                                 Ps[(ty * 4 + 1) * 65 + j],
                                 Ps[(ty * 4 + 2) * 65 + j],
                                 Ps[(ty * 4 + 3) * 65 + j]};
            const float4 v0 = *(const float4*)&Vs[j * 128 + tx * 8];
            const float4 v1 = *(const float4*)&Vs[j * 128 + tx * 8 + 4];
            const float vv[8] = {v0.x, v0.y, v0.z, v0.w, v1.x, v1.y, v1.z, v1.w};
            #pragma unroll
            for (int i = 0; i < 4; i++)
                #pragma unroll
                for (int k = 0; k < 8; k++)
                    o[i][k] += aa[i] * vv[k];
        }
    }

    // epilogue: normalize, write [b,s,h*128+d]
    #pragma unroll
    for (int i = 0; i < 4; i++) {
        const float inv = 1.0f / l_i[i];
        float* Og = g_attn + (size_t)(b * SEQ + q0 + ty * 4 + i) * DMODEL
                  + h * HEADDIM + tx * 8;
        float4 r0, r1;
        r0.x = o[i][0] * inv; r0.y = o[i][1] * inv;
        r0.z = o[i][2] * inv; r0.w = o[i][3] * inv;
        r1.x = o[i][4] * inv; r1.y = o[i][5] * inv;
        r1.z = o[i][6] * inv; r1.w = o[i][7] * inv;
        *(float4*)Og       = r0;
        *(float4*)(Og + 4) = r1;
    }
}

// ---------------------------------------------------------------------------
// Launch: qkv-proj(+clip) -> rope/transpose -> flash attention -> out-proj
// Inputs: 0=hidden_states f32, 1=position_ids i64 (unused: arange),
//         2=attention_mask f32 (unused: causal), 3=Wqkv_w f32, 4=out_w f32
// ---------------------------------------------------------------------------
extern "C" void kernel_launch(void* const* d_in, const int* in_sizes, int n_in,
                              void* d_out, int out_size)
{
    const float* hidden = (const float*)d_in[0];
    const float* Wqkv   = (const float*)d_in[3];
    const float* out_w  = (const float*)d_in[4];
    float*       out    = (float*)d_out;

    float *qkv_ptr, *attn_ptr;
    cudaGetSymbolAddress((void**)&qkv_ptr,  g_qkv);
    cudaGetSymbolAddress((void**)&attn_ptr, g_attn);

    // 1) QKV projection with clip: [4096,4096] x [6144,4096]^T
    sgemm_nt<true><<<dim3(QKV_N / 128, TOKENS / 128), 256>>>(
        hidden, Wqkv, qkv_ptr, TOKENS, QKV_N, DMODEL);

    // 2) RoPE + d-major transpose (Q pre-scaled by 1/sqrt(d))
    rope_kernel<<<TOKENS, 256>>>();

    // 3) causal flash attention
    cudaFuncSetAttribute(attn_kernel,
                         cudaFuncAttributeMaxDynamicSharedMemorySize,
                         ATTN_SMEM_BYTES);
    attn_kernel<<<dim3(SEQ / 64, NHEADS, BATCH), 256, ATTN_SMEM_BYTES>>>();

    // 4) output projection: [4096,4096] x [4096,4096]^T
    sgemm_nt<false><<<dim3(DMODEL / 128, TOKENS / 128), 256>>>(
        attn_ptr, out_w, out, TOKENS, DMODEL, DMODEL);
}

// round 2
// speedup vs baseline: 2.2724x; 2.2724x over previous
#include <cuda_runtime.h>
#include <math.h>
#include <stdint.h>

// ---------------------------------------------------------------------------
// Problem constants
// ---------------------------------------------------------------------------
#define BATCH     2
#define SEQ       2048
#define DMODEL    4096
#define NHEADS    32
#define KVHEADS   8
#define HEADDIM   128
#define QKV_N     (DMODEL + 2 * KVHEADS * HEADDIM)   // 6144
#define TOKENS    (BATCH * SEQ)                      // 4096
#define CLIP_V    8.0f
#define INV_SQRT_D 0.08838834764831845f              // 1/sqrt(128)

// ---------------------------------------------------------------------------
// Scratch (device globals; no dynamic allocation allowed)
// ---------------------------------------------------------------------------
__device__ float g_qkv [(size_t)TOKENS * QKV_N];                    // [b,s,6144]
__device__ float g_qt  [(size_t)BATCH * NHEADS  * HEADDIM * SEQ];   // [b,h,d,s], pre-scaled
__device__ float g_kt  [(size_t)BATCH * KVHEADS * HEADDIM * SEQ];   // [b,hk,d,s]
__device__ float g_attn[(size_t)TOKENS * DMODEL];                   // [b,s,4096]

// ---------------------------------------------------------------------------
// TF32 tensor-core GEMM:  C[M,N] = A[M,K] * B[N,K]^T  (row-major, K contig)
// 128x128x32 block tile, 8 warps (2x4), warp tile 64x32 (4x4 m16n8k8 mmas),
// 3-stage cp.async pipeline. smem rows padded to 36 floats -> conflict-free
// fragment loads (addr%32 = 4*(lane>>2)+(lane&3): 32 distinct banks).
// ---------------------------------------------------------------------------
#define BM 128
#define BN 128
#define BKg 32
#define BKP 36
#define STAGES 3
#define STAGE_FLOATS (BM * BKP + BN * BKP)          // 9216 floats / stage
#define GEMM_SMEM_BYTES (STAGES * STAGE_FLOATS * 4) // 110,592 B

__device__ __forceinline__ uint32_t f2tf(float x) {
    uint32_t r;
    asm("cvt.rna.tf32.f32 %0, %1;" : "=r"(r) : "f"(x));
    return r;
}
__device__ __forceinline__ void mma_tf32(float* c, const uint32_t* a, const uint32_t* b) {
    asm volatile(
        "mma.sync.aligned.m16n8k8.row.col.f32.tf32.tf32.f32 "
        "{%0,%1,%2,%3}, {%4,%5,%6,%7}, {%8,%9}, {%0,%1,%2,%3};"
        : "+f"(c[0]), "+f"(c[1]), "+f"(c[2]), "+f"(c[3])
        : "r"(a[0]), "r"(a[1]), "r"(a[2]), "r"(a[3]), "r"(b[0]), "r"(b[1]));
}
__device__ __forceinline__ void cp16(uint32_t s, const void* g) {
    asm volatile("cp.async.cg.shared.global [%0], [%1], 16;" :: "r"(s), "l"(g));
}

template <bool DO_CLIP>
__global__ __launch_bounds__(256)
void gemm_tf32(const float* __restrict__ A, const float* __restrict__ B,
               float* __restrict__ C, int M, int N, int K)
{
    extern __shared__ float sm[];
    const uint32_t smem_base = (uint32_t)__cvta_generic_to_shared(sm);

    const int tid = threadIdx.x;
    const int ln  = tid & 31;
    const int wid = tid >> 5;
    const int wm  = wid >> 2;          // 0..1
    const int wn  = wid & 3;           // 0..3
    const int m0  = blockIdx.y * BM;
    const int n0  = blockIdx.x * BN;

    const int lq = ln >> 2;            // 0..7
    const int lr = ln & 3;             // 0..3

    const float* Abase = A + (size_t)m0 * K;
    const float* Bbase = B + (size_t)n0 * K;

    // --- async stage loader: 1024 16B chunks A + 1024 B, 8 per thread ---
    auto load_stage = [&](int kt, int s) {
        const float* Ag = Abase + kt * BKg;
        const float* Bg = Bbase + kt * BKg;
        const uint32_t sa = smem_base + (uint32_t)(s * STAGE_FLOATS) * 4u;
        const uint32_t sb = sa + BM * BKP * 4u;
        #pragma unroll
        for (int r = 0; r < 4; r++) {
            const int i   = r * 256 + tid;
            const int row = i >> 3;
            const int kc  = (i & 7) << 2;
            cp16(sa + (uint32_t)(row * BKP + kc) * 4u, Ag + (size_t)row * K + kc);
            cp16(sb + (uint32_t)(row * BKP + kc) * 4u, Bg + (size_t)row * K + kc);
        }
        asm volatile("cp.async.commit_group;");
    };

    #pragma unroll
    for (int s = 0; s < STAGES - 1; s++) load_stage(s, s);

    float acc[4][4][4];
    #pragma unroll
    for (int a = 0; a < 4; a++)
        #pragma unroll
        for (int b = 0; b < 4; b++)
            #pragma unroll
            for (int c = 0; c < 4; c++) acc[a][b][c] = 0.0f;

    const int nk = K / BKg;
    for (int kt = 0; kt < nk; kt++) {
        if (kt + STAGES - 1 < nk) load_stage(kt + STAGES - 1, (kt + STAGES - 1) % STAGES);
        else asm volatile("cp.async.commit_group;");
        asm volatile("cp.async.wait_group %0;" :: "n"(STAGES - 1));
        __syncthreads();

        const float* As_ = sm + (kt % STAGES) * STAGE_FLOATS;
        const float* Bs_ = As_ + BM * BKP;

        #pragma unroll
        for (int ks = 0; ks < 4; ks++) {
            const int k0 = ks * 8 + lr;
            uint32_t af[4][4], bf[4][2];
            #pragma unroll
            for (int mt = 0; mt < 4; mt++) {
                const float* p = As_ + (wm * 64 + mt * 16 + lq) * BKP + k0;
                af[mt][0] = f2tf(p[0]);
                af[mt][2] = f2tf(p[4]);
                af[mt][1] = f2tf(p[8 * BKP]);
                af[mt][3] = f2tf(p[8 * BKP + 4]);
            }
            #pragma unroll
            for (int nt = 0; nt < 4; nt++) {
                const float* p = Bs_ + (wn * 32 + nt * 8 + lq) * BKP + k0;
                bf[nt][0] = f2tf(p[0]);
                bf[nt][1] = f2tf(p[4]);
            }
            #pragma unroll
            for (int mt = 0; mt < 4; mt++)
                #pragma unroll
                for (int nt = 0; nt < 4; nt++)
                    mma_tf32(acc[mt][nt], af[mt], bf[nt]);
        }
        __syncthreads();
    }

    // --- epilogue: float2 stores, optional clip ---
    float* Cg = C + (size_t)(m0 + wm * 64) * N + n0 + wn * 32;
    #pragma unroll
    for (int mt = 0; mt < 4; mt++) {
        #pragma unroll
        for (int nt = 0; nt < 4; nt++) {
            const int row = mt * 16 + lq;
            const int col = nt * 8 + lr * 2;
            float2 v0 = make_float2(acc[mt][nt][0], acc[mt][nt][1]);
            float2 v1 = make_float2(acc[mt][nt][2], acc[mt][nt][3]);
            if (DO_CLIP) {
                v0.x = fminf(fmaxf(v0.x, -CLIP_V), CLIP_V);
                v0.y = fminf(fmaxf(v0.y, -CLIP_V), CLIP_V);
                v1.x = fminf(fmaxf(v1.x, -CLIP_V), CLIP_V);
                v1.y = fminf(fmaxf(v1.y, -CLIP_V), CLIP_V);
            }
            *(float2*)(Cg + (size_t)row * N + col)       = v0;
            *(float2*)(Cg + (size_t)(row + 8) * N + col) = v1;
        }
    }
}

// ---------------------------------------------------------------------------
// RoPE + transpose: reads g_qkv rows, applies rotation (and 1/sqrt(d) to Q),
// scatters into d-major layouts g_qt[b,h,d,s] / g_kt[b,hk,d,s].
// position_ids is provably arange(S) broadcast -> use s directly.
// ---------------------------------------------------------------------------
__global__ __launch_bounds__(256)
void rope_kernel()
{
    const int token = blockIdx.x;          // 0..4095
    const int b    = token / SEQ;
    const int spos = token - b * SEQ;
    const float* row = g_qkv + (size_t)token * QKV_N;
    const float posf = (float)spos;

    for (int idx = threadIdx.x; idx < (NHEADS + KVHEADS) * 64; idx += 256) {
        const int h = idx >> 6;            // 0..39 (0..31 = Q heads, 32..39 = K heads)
        const int j = idx & 63;            // rotation pair index
        const float freq = powf(500000.0f, -(float)j * (1.0f / 64.0f));
        float s, c;
        sincosf(posf * freq, &s, &c);

        const float x1 = row[h * HEADDIM + j];
        const float x2 = row[h * HEADDIM + 64 + j];
        const float y1 = x1 * c - x2 * s;
        const float y2 = x2 * c + x1 * s;

        if (h < NHEADS) {
            float* q = g_qt + ((size_t)(b * NHEADS + h) * HEADDIM) * SEQ;
            q[(size_t)j * SEQ + spos]        = y1 * INV_SQRT_D;
            q[(size_t)(j + 64) * SEQ + spos] = y2 * INV_SQRT_D;
        } else {
            float* k = g_kt + ((size_t)(b * KVHEADS + (h - NHEADS)) * HEADDIM) * SEQ;
            k[(size_t)j * SEQ + spos]        = y1;
            k[(size_t)(j + 64) * SEQ + spos] = y2;
        }
    }
}

// ---------------------------------------------------------------------------
// Fused causal flash attention, fp32 SIMT (unchanged from R1).
// ---------------------------------------------------------------------------
#define ATTN_SMEM_FLOATS (8192 + 8192 + 8192 + 64 * 65)
#define ATTN_SMEM_BYTES  (ATTN_SMEM_FLOATS * 4)

__global__ __launch_bounds__(256, 2)
void attn_kernel()
{
    extern __shared__ float sm[];
    float* Qt = sm;               // [d][m]  d-major
    float* Kt = sm + 8192;        // [d][n]
    float* Vs = sm + 16384;       // [n][d]
    float* Ps = sm + 24576;       // [m][n]  row pitch 65

    const int qt = blockIdx.x;    // query tile (0..31)
    const int h  = blockIdx.y;    // head
    const int b  = blockIdx.z;    // batch
    const int hk = h >> 2;        // GQA: 4 q-heads share one kv-head
    const int q0 = qt * 64;

    const int tid = threadIdx.x;
    const int ty  = tid >> 4;     // 0..15 -> rows ty*4..+3
    const int tx  = tid & 15;     // 0..15 -> cols tx*4..+3 (A) / tx*8..+7 (C)

    const float* Qg = g_qt + ((size_t)(b * NHEADS + h) * HEADDIM) * SEQ + q0;
    const float* Kg = g_kt + ((size_t)(b * KVHEADS + hk) * HEADDIM) * SEQ;
    const float* Vg = g_qkv + (size_t)b * SEQ * QKV_N + DMODEL + KVHEADS * HEADDIM + hk * HEADDIM;

    for (int i = tid; i < 2048; i += 256) {
        const int d  = i >> 4;
        const int m4 = (i & 15) << 2;
        *(float4*)&Qt[d * 64 + m4] = *(const float4*)&Qg[(size_t)d * SEQ + m4];
    }

    float m_i[4], l_i[4], o[4][8];
    #pragma unroll
    for (int i = 0; i < 4; i++) {
        m_i[i] = -3.0e38f; l_i[i] = 0.0f;
        #pragma unroll
        for (int k = 0; k < 8; k++) o[i][k] = 0.0f;
    }

    for (int jt = 0; jt <= qt; jt++) {
        const int j0 = jt * 64;
        __syncthreads();

        for (int i = tid; i < 2048; i += 256) {
            const int d  = i >> 4;
            const int m4 = (i & 15) << 2;
            *(float4*)&Kt[d * 64 + m4] = *(const float4*)&Kg[(size_t)d * SEQ + j0 + m4];
        }
        for (int i = tid; i < 2048; i += 256) {
            const int j  = i >> 5;
            const int d4 = (i & 31) << 2;
            *(float4*)&Vs[j * 128 + d4] = *(const float4*)&Vg[(size_t)(j0 + j) * QKV_N + d4];
        }
        __syncthreads();

        float sacc[4][4];
        #pragma unroll
        for (int i = 0; i < 4; i++)
            #pragma unroll
            for (int j = 0; j < 4; j++) sacc[i][j] = 0.0f;

        #pragma unroll 4
        for (int d = 0; d < 128; d++) {
            const float4 a = *(const float4*)&Qt[d * 64 + ty * 4];
            const float4 v = *(const float4*)&Kt[d * 64 + tx * 4];
            const float av[4] = {a.x, a.y, a.z, a.w};
            const float bv[4] = {v.x, v.y, v.z, v.w};
            #pragma unroll
            for (int i = 0; i < 4; i++)
                #pragma unroll
                for (int j = 0; j < 4; j++)
                    sacc[i][j] += av[i] * bv[j];
        }

        if (jt == qt) {
            #pragma unroll
            for (int i = 0; i < 4; i++)
                #pragma unroll
                for (int j = 0; j < 4; j++)
                    if (tx * 4 + j > ty * 4 + i) sacc[i][j] = -3.0e38f;
        }

        #pragma unroll
        for (int i = 0; i < 4; i++) {
            float tm = fmaxf(fmaxf(sacc[i][0], sacc[i][1]),
                             fmaxf(sacc[i][2], sacc[i][3]));
            #pragma unroll
            for (int off = 8; off >= 1; off >>= 1)
                tm = fmaxf(tm, __shfl_xor_sync(0xffffffffu, tm, off));
            const float mnew  = fmaxf(m_i[i], tm);
            const float alpha = __expf(m_i[i] - mnew);
            float rs = 0.0f;
            #pragma unroll
            for (int j = 0; j < 4; j++) {
                sacc[i][j] = __expf(sacc[i][j] - mnew);
                rs += sacc[i][j];
            }
            #pragma unroll
            for (int off = 8; off >= 1; off >>= 1)
                rs += __shfl_xor_sync(0xffffffffu, rs, off);
            l_i[i] = l_i[i] * alpha + rs;
            m_i[i] = mnew;
            #pragma unroll
            for (int k = 0; k < 8; k++) o[i][k] *= alpha;
            #pragma unroll
            for (int j = 0; j < 4; j++)
                Ps[(ty * 4 + i) * 65 + tx * 4 + j] = sacc[i][j];
        }
        __syncthreads();

        #pragma unroll 2
        for (int j = 0; j < 64; j++) {
            const float aa[4] = {Ps[(ty * 4 + 0) * 65 + j],
                                 Ps[(ty * 4 + 1) * 65 + j],
                                 Ps[(ty * 4 + 2) * 65 + j],
                                 Ps[(ty * 4 + 3) * 65 + j]};
            const float4 v0 = *(const float4*)&Vs[j * 128 + tx * 8];
            const float4 v1 = *(const float4*)&Vs[j * 128 + tx * 8 + 4];
            const float vv[8] = {v0.x, v0.y, v0.z, v0.w, v1.x, v1.y, v1.z, v1.w};
            #pragma unroll
            for (int i = 0; i < 4; i++)
                #pragma unroll
                for (int k = 0; k < 8; k++)
                    o[i][k] += aa[i] * vv[k];
        }
    }

    #pragma unroll
    for (int i = 0; i < 4; i++) {
        const float inv = 1.0f / l_i[i];
        float* Og = g_attn + (size_t)(b * SEQ + q0 + ty * 4 + i) * DMODEL
                  + h * HEADDIM + tx * 8;
        float4 r0, r1;
        r0.x = o[i][0] * inv; r0.y = o[i][1] * inv;
        r0.z = o[i][2] * inv; r0.w = o[i][3] * inv;
        r1.x = o[i][4] * inv; r1.y = o[i][5] * inv;
        r1.z = o[i][6] * inv; r1.w = o[i][7] * inv;
        *(float4*)Og       = r0;
        *(float4*)(Og + 4) = r1;
    }
}

// ---------------------------------------------------------------------------
// Launch: tf32 qkv-proj(+clip) -> rope/transpose -> flash attn -> tf32 out-proj
// Inputs: 0=hidden_states f32, 1=position_ids i64 (unused: arange),
//         2=attention_mask f32 (unused: causal), 3=Wqkv_w f32, 4=out_w f32
// ---------------------------------------------------------------------------
extern "C" void kernel_launch(void* const* d_in, const int* in_sizes, int n_in,
                              void* d_out, int out_size)
{
    const float* hidden = (const float*)d_in[0];
    const float* Wqkv   = (const float*)d_in[3];
    const float* out_w  = (const float*)d_in[4];
    float*       out    = (float*)d_out;

    float *qkv_ptr, *attn_ptr;
    cudaGetSymbolAddress((void**)&qkv_ptr,  g_qkv);
    cudaGetSymbolAddress((void**)&attn_ptr, g_attn);

    cudaFuncSetAttribute(gemm_tf32<true>,
                         cudaFuncAttributeMaxDynamicSharedMemorySize, GEMM_SMEM_BYTES);
    cudaFuncSetAttribute(gemm_tf32<false>,
                         cudaFuncAttributeMaxDynamicSharedMemorySize, GEMM_SMEM_BYTES);
    cudaFuncSetAttribute(attn_kernel,
                         cudaFuncAttributeMaxDynamicSharedMemorySize, ATTN_SMEM_BYTES);

    // 1) QKV projection with clip: [4096,4096] x [6144,4096]^T
    gemm_tf32<true><<<dim3(QKV_N / BN, TOKENS / BM), 256, GEMM_SMEM_BYTES>>>(
        hidden, Wqkv, qkv_ptr, TOKENS, QKV_N, DMODEL);

    // 2) RoPE + d-major transpose (Q pre-scaled by 1/sqrt(d))
    rope_kernel<<<TOKENS, 256>>>();

    // 3) causal flash attention (fp32 SIMT)
    attn_kernel<<<dim3(SEQ / 64, NHEADS, BATCH), 256, ATTN_SMEM_BYTES>>>();

    // 4) output projection: [4096,4096] x [4096,4096]^T
    gemm_tf32<false><<<dim3(DMODEL / BN, TOKENS / BM), 256, GEMM_SMEM_BYTES>>>(
        attn_ptr, out_w, out, TOKENS, DMODEL, DMODEL);
}

// round 3
// speedup vs baseline: 3.7915x; 1.6685x over previous
#include <cuda_runtime.h>
#include <math.h>
#include <stdint.h>

// ---------------------------------------------------------------------------
// Problem constants
// ---------------------------------------------------------------------------
#define BATCH     2
#define SEQ       2048
#define DMODEL    4096
#define NHEADS    32
#define KVHEADS   8
#define HEADDIM   128
#define QKV_N     (DMODEL + 2 * KVHEADS * HEADDIM)   // 6144
#define TOKENS    (BATCH * SEQ)                      // 4096
#define CLIP_V    8.0f
#define INV_SQRT_D 0.08838834764831845f              // 1/sqrt(128)

// ---------------------------------------------------------------------------
// Scratch (device globals; no dynamic allocation allowed)
// ---------------------------------------------------------------------------
__device__ float g_qkv  [(size_t)TOKENS * QKV_N];                    // [b,s,6144]
__device__ float g_q    [(size_t)BATCH * NHEADS  * SEQ * HEADDIM];   // [b,h,s,d] tf32-rounded, prescaled
__device__ float g_k    [(size_t)BATCH * KVHEADS * SEQ * HEADDIM];   // [b,hk,s,d] tf32-rounded
__device__ float g_vt   [(size_t)BATCH * KVHEADS * HEADDIM * SEQ];   // [b,hk,d,s] tf32-rounded
__device__ float g_attn [(size_t)TOKENS * DMODEL];                   // [b,s,4096] tf32-rounded
__device__ float g_hid_r[(size_t)TOKENS * DMODEL];                   // rounded hidden
__device__ float g_wq_r [(size_t)QKV_N  * DMODEL];                   // rounded Wqkv
__device__ float g_wo_r [(size_t)DMODEL * DMODEL];                   // rounded out_w

// ---------------------------------------------------------------------------
// helpers
// ---------------------------------------------------------------------------
__device__ __forceinline__ uint32_t f2tf(float x) {
    uint32_t r;
    asm("cvt.rna.tf32.f32 %0, %1;" : "=r"(r) : "f"(x));
    return r;
}
__device__ __forceinline__ float tfr(float x) { return __uint_as_float(f2tf(x)); }
__device__ __forceinline__ void mma_tf32(float* c, const uint32_t* a, const uint32_t* b) {
    asm volatile(
        "mma.sync.aligned.m16n8k8.row.col.f32.tf32.tf32.f32 "
        "{%0,%1,%2,%3}, {%4,%5,%6,%7}, {%8,%9}, {%0,%1,%2,%3};"
        : "+f"(c[0]), "+f"(c[1]), "+f"(c[2]), "+f"(c[3])
        : "r"(a[0]), "r"(a[1]), "r"(a[2]), "r"(a[3]), "r"(b[0]), "r"(b[1]));
}
__device__ __forceinline__ void cp16(uint32_t s, const void* g) {
    asm volatile("cp.async.cg.shared.global [%0], [%1], 16;" :: "r"(s), "l"(g));
}

// ---------------------------------------------------------------------------
// elementwise tf32 pre-round (float4 grid-stride)
// ---------------------------------------------------------------------------
__global__ __launch_bounds__(256)
void round_tf32_kernel(const float4* __restrict__ in, float4* __restrict__ out, int n4)
{
    for (int i = blockIdx.x * blockDim.x + threadIdx.x; i < n4; i += gridDim.x * blockDim.x) {
        float4 v = in[i];
        v.x = tfr(v.x); v.y = tfr(v.y); v.z = tfr(v.z); v.w = tfr(v.w);
        out[i] = v;
    }
}

// ---------------------------------------------------------------------------
// TF32 tensor-core GEMM:  C[M,N] = A[M,K] * B[N,K]^T  (operands pre-rounded)
// 128x128x32 block tile, 8 warps (2x4), warp tile 64x32, 3-stage cp.async.
// ---------------------------------------------------------------------------
#define BM 128
#define BN 128
#define BKg 32
#define BKP 36
#define STAGES 3
#define STAGE_FLOATS (BM * BKP + BN * BKP)
#define GEMM_SMEM_BYTES (STAGES * STAGE_FLOATS * 4)

template <bool DO_CLIP>
__global__ __launch_bounds__(256)
void gemm_tf32(const float* __restrict__ A, const float* __restrict__ B,
               float* __restrict__ C, int M, int N, int K)
{
    extern __shared__ float sm[];
    const uint32_t smem_base = (uint32_t)__cvta_generic_to_shared(sm);

    const int tid = threadIdx.x;
    const int ln  = tid & 31;
    const int wid = tid >> 5;
    const int wm  = wid >> 2;
    const int wn  = wid & 3;
    const int m0  = blockIdx.y * BM;
    const int n0  = blockIdx.x * BN;
    const int lq  = ln >> 2;
    const int lr  = ln & 3;

    const float* Abase = A + (size_t)m0 * K;
    const float* Bbase = B + (size_t)n0 * K;

    auto load_stage = [&](int kt, int s) {
        const float* Ag = Abase + kt * BKg;
        const float* Bg = Bbase + kt * BKg;
        const uint32_t sa = smem_base + (uint32_t)(s * STAGE_FLOATS) * 4u;
        const uint32_t sb = sa + BM * BKP * 4u;
        #pragma unroll
        for (int r = 0; r < 4; r++) {
            const int i   = r * 256 + tid;
            const int row = i >> 3;
            const int kc  = (i & 7) << 2;
            cp16(sa + (uint32_t)(row * BKP + kc) * 4u, Ag + (size_t)row * K + kc);
            cp16(sb + (uint32_t)(row * BKP + kc) * 4u, Bg + (size_t)row * K + kc);
        }
        asm volatile("cp.async.commit_group;");
    };

    #pragma unroll
    for (int s = 0; s < STAGES - 1; s++) load_stage(s, s);

    float acc[4][4][4];
    #pragma unroll
    for (int a = 0; a < 4; a++)
        #pragma unroll
        for (int b = 0; b < 4; b++)
            #pragma unroll
            for (int c = 0; c < 4; c++) acc[a][b][c] = 0.0f;

    const int nk = K / BKg;
    for (int kt = 0; kt < nk; kt++) {
        if (kt + STAGES - 1 < nk) load_stage(kt + STAGES - 1, (kt + STAGES - 1) % STAGES);
        else asm volatile("cp.async.commit_group;");
        asm volatile("cp.async.wait_group %0;" :: "n"(STAGES - 1));
        __syncthreads();

        const float* As_ = sm + (kt % STAGES) * STAGE_FLOATS;
        const float* Bs_ = As_ + BM * BKP;

        #pragma unroll
        for (int ks = 0; ks < 4; ks++) {
            const int k0 = ks * 8 + lr;
            uint32_t af[4][4], bf[4][2];
            #pragma unroll
            for (int mt = 0; mt < 4; mt++) {
                const float* p = As_ + (wm * 64 + mt * 16 + lq) * BKP + k0;
                af[mt][0] = __float_as_uint(p[0]);
                af[mt][2] = __float_as_uint(p[4]);
                af[mt][1] = __float_as_uint(p[8 * BKP]);
                af[mt][3] = __float_as_uint(p[8 * BKP + 4]);
            }
            #pragma unroll
            for (int nt = 0; nt < 4; nt++) {
                const float* p = Bs_ + (wn * 32 + nt * 8 + lq) * BKP + k0;
                bf[nt][0] = __float_as_uint(p[0]);
                bf[nt][1] = __float_as_uint(p[4]);
            }
            #pragma unroll
            for (int mt = 0; mt < 4; mt++)
                #pragma unroll
                for (int nt = 0; nt < 4; nt++)
                    mma_tf32(acc[mt][nt], af[mt], bf[nt]);
        }
        __syncthreads();
    }

    float* Cg = C + (size_t)(m0 + wm * 64) * N + n0 + wn * 32;
    #pragma unroll
    for (int mt = 0; mt < 4; mt++) {
        #pragma unroll
        for (int nt = 0; nt < 4; nt++) {
            const int row = mt * 16 + lq;
            const int col = nt * 8 + lr * 2;
            float2 v0 = make_float2(acc[mt][nt][0], acc[mt][nt][1]);
            float2 v1 = make_float2(acc[mt][nt][2], acc[mt][nt][3]);
            if (DO_CLIP) {
                v0.x = fminf(fmaxf(v0.x, -CLIP_V), CLIP_V);
                v0.y = fminf(fmaxf(v0.y, -CLIP_V), CLIP_V);
                v1.x = fminf(fmaxf(v1.x, -CLIP_V), CLIP_V);
                v1.y = fminf(fmaxf(v1.y, -CLIP_V), CLIP_V);
            }
            *(float2*)(Cg + (size_t)row * N + col)       = v0;
            *(float2*)(Cg + (size_t)(row + 8) * N + col) = v1;
        }
    }
}

// ---------------------------------------------------------------------------
// RoPE + layout: g_qkv -> g_q [b,h,s,d] (prescaled, tf32-rounded),
//                         g_k [b,hk,s,d] (rounded), g_vt [b,hk,d,s] (rounded).
// position_ids provably arange(S); attention_mask provably causal.
// ---------------------------------------------------------------------------
__global__ __launch_bounds__(256)
void rope_kernel()
{
    const int token = blockIdx.x;
    const int b    = token / SEQ;
    const int spos = token - b * SEQ;
    const float* row = g_qkv + (size_t)token * QKV_N;
    const float posf = (float)spos;

    for (int idx = threadIdx.x; idx < (NHEADS + KVHEADS) * 64; idx += 256) {
        const int h = idx >> 6;
        const int j = idx & 63;
        const float freq = powf(500000.0f, -(float)j * (1.0f / 64.0f));
        float s, c;
        sincosf(posf * freq, &s, &c);

        const float x1 = row[h * HEADDIM + j];
        const float x2 = row[h * HEADDIM + 64 + j];
        const float y1 = x1 * c - x2 * s;
        const float y2 = x2 * c + x1 * s;

        if (h < NHEADS) {
            float* q = g_q + ((size_t)(b * NHEADS + h) * SEQ + spos) * HEADDIM;
            q[j]      = tfr(y1 * INV_SQRT_D);
            q[j + 64] = tfr(y2 * INV_SQRT_D);
        } else {
            float* k = g_k + ((size_t)(b * KVHEADS + (h - NHEADS)) * SEQ + spos) * HEADDIM;
            k[j]      = tfr(y1);
            k[j + 64] = tfr(y2);
        }
    }

    // V transpose + round: [s,d] -> [d,s]
    const float* vrow = row + DMODEL + KVHEADS * HEADDIM;
    for (int idx = threadIdx.x; idx < KVHEADS * HEADDIM; idx += 256) {
        const int hk = idx >> 7;
        const int d  = idx & 127;
        g_vt[((size_t)(b * KVHEADS + hk) * HEADDIM + d) * SEQ + spos] = tfr(vrow[hk * HEADDIM + d]);
    }
}

// ---------------------------------------------------------------------------
// Tensor-core causal flash attention (tf32 mma).
// CTA: 64 q-rows x (head,batch). 4 warps, each owns 16 q-rows.
// smem: Qs[64][132], KP[64][132] (K tile, then reused for P), Vt[128][68].
// ---------------------------------------------------------------------------
#define QK_PITCH 132
#define V_PITCH  68
#define ATTN_SMEM_FLOATS (2 * 64 * QK_PITCH + 128 * V_PITCH)
#define ATTN_SMEM_BYTES  (ATTN_SMEM_FLOATS * 4)   // 102,400

__global__ __launch_bounds__(128, 2)
void attn_kernel()
{
    extern __shared__ float sm[];
    float* Qs = sm;                       // [64][132]
    float* KP = sm + 64 * QK_PITCH;       // [64][132]
    float* Vt = sm + 2 * 64 * QK_PITCH;   // [128][68]
    const uint32_t smem_base = (uint32_t)__cvta_generic_to_shared(sm);
    const uint32_t kp_base   = smem_base + 64 * QK_PITCH * 4u;
    const uint32_t vt_base   = smem_base + 2 * 64 * QK_PITCH * 4u;

    const int qt = blockIdx.x;
    const int h  = blockIdx.y;
    const int b  = blockIdx.z;
    const int hk = h >> 2;
    const int q0 = qt * 64;

    const int tid = threadIdx.x;
    const int ln  = tid & 31;
    const int wid = tid >> 5;
    const int lq  = ln >> 2;
    const int lr  = ln & 3;

    const float* Qg = g_q  + ((size_t)(b * NHEADS  + h)  * SEQ + q0) * HEADDIM;
    const float* Kg = g_k  + ((size_t)(b * KVHEADS + hk) * SEQ) * HEADDIM;
    const float* Vg = g_vt + ((size_t)(b * KVHEADS + hk) * HEADDIM) * SEQ;

    // load Q tile (pre-rounded, prescaled): 64x128, 16 float4/thread
    for (int i = tid; i < 2048; i += 128) {
        const int r  = i >> 5;
        const int c4 = (i & 31) << 2;
        cp16(smem_base + (uint32_t)(r * QK_PITCH + c4) * 4u, Qg + (size_t)r * HEADDIM + c4);
    }
    asm volatile("cp.async.commit_group;");

    float m0 = -3.0e38f, m1 = -3.0e38f, l0 = 0.0f, l1 = 0.0f;
    float o[16][4];
    #pragma unroll
    for (int nt = 0; nt < 16; nt++)
        #pragma unroll
        for (int c = 0; c < 4; c++) o[nt][c] = 0.0f;

    for (int jt = 0; jt <= qt; jt++) {
        const int j0 = jt * 64;
        __syncthreads();   // prev PV done with KP/Vt

        for (int i = tid; i < 2048; i += 128) {        // K tile [j][d]
            const int r  = i >> 5;
            const int c4 = (i & 31) << 2;
            cp16(kp_base + (uint32_t)(r * QK_PITCH + c4) * 4u,
                 Kg + (size_t)(j0 + r) * HEADDIM + c4);
        }
        for (int i = tid; i < 2048; i += 128) {        // V tile [d][j]
            const int r  = i >> 4;
            const int c4 = (i & 15) << 2;
            cp16(vt_base + (uint32_t)(r * V_PITCH + c4) * 4u,
                 Vg + (size_t)r * SEQ + j0 + c4);
        }
        asm volatile("cp.async.commit_group;");
        asm volatile("cp.async.wait_group 0;");
        __syncthreads();

        // ---- S = Q K^T : 8 n-tiles x 16 k-steps ----
        float s_[8][4];
        #pragma unroll
        for (int t = 0; t < 8; t++)
            #pragma unroll
            for (int c = 0; c < 4; c++) s_[t][c] = 0.0f;

        #pragma unroll
        for (int k0 = 0; k0 < 128; k0 += 8) {
            uint32_t a[4];
            const float* ap = Qs + (wid * 16 + lq) * QK_PITCH + k0 + lr;
            a[0] = __float_as_uint(ap[0]);
            a[1] = __float_as_uint(ap[8 * QK_PITCH]);
            a[2] = __float_as_uint(ap[4]);
            a[3] = __float_as_uint(ap[8 * QK_PITCH + 4]);
            #pragma unroll
            for (int t = 0; t < 8; t++) {
                const float* bp = KP + (t * 8 + lq) * QK_PITCH + k0 + lr;
                uint32_t bb[2] = { __float_as_uint(bp[0]), __float_as_uint(bp[4]) };
                mma_tf32(s_[t], a, bb);
            }
        }

        if (jt == qt) {   // causal mask on diagonal tile (j0 == q0)
            const int r0 = wid * 16 + lq;
            #pragma unroll
            for (int t = 0; t < 8; t++) {
                const int c0 = t * 8 + 2 * lr;
                if (c0     > r0)     s_[t][0] = -3.0e38f;
                if (c0 + 1 > r0)     s_[t][1] = -3.0e38f;
                if (c0     > r0 + 8) s_[t][2] = -3.0e38f;
                if (c0 + 1 > r0 + 8) s_[t][3] = -3.0e38f;
            }
        }

        // ---- online softmax (rows lq / lq+8, reduce over 4 lanes lr) ----
        float mx0 = -3.0e38f, mx1 = -3.0e38f;
        #pragma unroll
        for (int t = 0; t < 8; t++) {
            mx0 = fmaxf(mx0, fmaxf(s_[t][0], s_[t][1]));
            mx1 = fmaxf(mx1, fmaxf(s_[t][2], s_[t][3]));
        }
        mx0 = fmaxf(mx0, __shfl_xor_sync(0xffffffffu, mx0, 1));
        mx0 = fmaxf(mx0, __shfl_xor_sync(0xffffffffu, mx0, 2));
        mx1 = fmaxf(mx1, __shfl_xor_sync(0xffffffffu, mx1, 1));
        mx1 = fmaxf(mx1, __shfl_xor_sync(0xffffffffu, mx1, 2));

        const float mn0 = fmaxf(m0, mx0);
        const float mn1 = fmaxf(m1, mx1);
        const float al0 = __expf(m0 - mn0);
        const float al1 = __expf(m1 - mn1);
        float rs0 = 0.0f, rs1 = 0.0f;
        #pragma unroll
        for (int t = 0; t < 8; t++) {
            s_[t][0] = __expf(s_[t][0] - mn0); rs0 += s_[t][0];
            s_[t][1] = __expf(s_[t][1] - mn0); rs0 += s_[t][1];
            s_[t][2] = __expf(s_[t][2] - mn1); rs1 += s_[t][2];
            s_[t][3] = __expf(s_[t][3] - mn1); rs1 += s_[t][3];
        }
        rs0 += __shfl_xor_sync(0xffffffffu, rs0, 1);
        rs0 += __shfl_xor_sync(0xffffffffu, rs0, 2);
        rs1 += __shfl_xor_sync(0xffffffffu, rs1, 1);
        rs1 += __shfl_xor_sync(0xffffffffu, rs1, 2);
        l0 = l0 * al0 + rs0;  m0 = mn0;
        l1 = l1 * al1 + rs1;  m1 = mn1;
        #pragma unroll
        for (int nt = 0; nt < 16; nt++) {
            o[nt][0] *= al0; o[nt][1] *= al0;
            o[nt][2] *= al1; o[nt][3] *= al1;
        }

        __syncthreads();   // all warps done reading K from KP

        // ---- store P (tf32-rounded) into KP as [m][j] ----
        {
            float* p0 = KP + (wid * 16 + lq) * QK_PITCH + 2 * lr;
            float* p1 = p0 + 8 * QK_PITCH;
            #pragma unroll
            for (int t = 0; t < 8; t++) {
                p0[t * 8]     = tfr(s_[t][0]);
                p0[t * 8 + 1] = tfr(s_[t][1]);
                p1[t * 8]     = tfr(s_[t][2]);
                p1[t * 8 + 1] = tfr(s_[t][3]);
            }
        }
        __syncthreads();

        // ---- O += P Vt : 16 n-tiles (d) x 8 k-steps (j) ----
        #pragma unroll
        for (int k0 = 0; k0 < 64; k0 += 8) {
            uint32_t a[4];
            const float* ap = KP + (wid * 16 + lq) * QK_PITCH + k0 + lr;
            a[0] = __float_as_uint(ap[0]);
            a[1] = __float_as_uint(ap[8 * QK_PITCH]);
            a[2] = __float_as_uint(ap[4]);
            a[3] = __float_as_uint(ap[8 * QK_PITCH + 4]);
            #pragma unroll
            for (int nt = 0; nt < 16; nt++) {
                const float* bp = Vt + (nt * 8 + lq) * V_PITCH + k0 + lr;
                uint32_t bb[2] = { __float_as_uint(bp[0]), __float_as_uint(bp[4]) };
                mma_tf32(o[nt], a, bb);
            }
        }
    }

    // ---- epilogue: normalize, tf32-round (feeds out-proj), write [b,s,h*128+d]
    const float inv0 = 1.0f / l0;
    const float inv1 = 1.0f / l1;
    const int s0 = q0 + wid * 16 + lq;
    float* O0 = g_attn + (size_t)(b * SEQ + s0) * DMODEL + h * HEADDIM + 2 * lr;
    float* O1 = O0 + (size_t)8 * DMODEL;
    #pragma unroll
    for (int nt = 0; nt < 16; nt++) {
        float2 v0 = make_float2(tfr(o[nt][0] * inv0), tfr(o[nt][1] * inv0));
        float2 v1 = make_float2(tfr(o[nt][2] * inv1), tfr(o[nt][3] * inv1));
        *(float2*)(O0 + nt * 8) = v0;
        *(float2*)(O1 + nt * 8) = v1;
    }
}

// ---------------------------------------------------------------------------
// Launch sequence
// Inputs: 0=hidden_states f32, 1=position_ids i64 (arange), 2=attention_mask
//         (causal), 3=Wqkv_w f32, 4=out_w f32
// ---------------------------------------------------------------------------
extern "C" void kernel_launch(void* const* d_in, const int* in_sizes, int n_in,
                              void* d_out, int out_size)
{
    const float* hidden = (const float*)d_in[0];
    const float* Wqkv   = (const float*)d_in[3];
    const float* out_w  = (const float*)d_in[4];
    float*       out    = (float*)d_out;

    float *qkv_p, *attn_p, *hid_p, *wq_p, *wo_p;
    cudaGetSymbolAddress((void**)&qkv_p,  g_qkv);
    cudaGetSymbolAddress((void**)&attn_p, g_attn);
    cudaGetSymbolAddress((void**)&hid_p,  g_hid_r);
    cudaGetSymbolAddress((void**)&wq_p,   g_wq_r);
    cudaGetSymbolAddress((void**)&wo_p,   g_wo_r);

    cudaFuncSetAttribute(gemm_tf32<true>,
                         cudaFuncAttributeMaxDynamicSharedMemorySize, GEMM_SMEM_BYTES);
    cudaFuncSetAttribute(gemm_tf32<false>,
                         cudaFuncAttributeMaxDynamicSharedMemorySize, GEMM_SMEM_BYTES);
    cudaFuncSetAttribute(attn_kernel,
                         cudaFuncAttributeMaxDynamicSharedMemorySize, ATTN_SMEM_BYTES);

    // 0) pre-round operands to tf32
    round_tf32_kernel<<<1184, 256>>>((const float4*)hidden, (float4*)hid_p,
                                     TOKENS * DMODEL / 4);
    round_tf32_kernel<<<1184, 256>>>((const float4*)Wqkv, (float4*)wq_p,
                                     QKV_N * DMODEL / 4);
    round_tf32_kernel<<<1184, 256>>>((const float4*)out_w, (float4*)wo_p,
                                     DMODEL * DMODEL / 4);

    // 1) QKV projection with clip
    gemm_tf32<true><<<dim3(QKV_N / BN, TOKENS / BM), 256, GEMM_SMEM_BYTES>>>(
        hid_p, wq_p, qkv_p, TOKENS, QKV_N, DMODEL);

    // 2) RoPE + layouts (tf32-rounded outputs)
    rope_kernel<<<TOKENS, 256>>>();

    // 3) tensor-core causal flash attention
    attn_kernel<<<dim3(SEQ / 64, NHEADS, BATCH), 128, ATTN_SMEM_BYTES>>>();

    // 4) output projection
    gemm_tf32<false><<<dim3(DMODEL / BN, TOKENS / BM), 256, GEMM_SMEM_BYTES>>>(
        attn_p, wo_p, out, TOKENS, DMODEL, DMODEL);
}

// round 5
// speedup vs baseline: 3.9663x; 1.0461x over previous
#include <cuda_runtime.h>
#include <math.h>
#include <stdint.h>

// ---------------------------------------------------------------------------
// Problem constants
// ---------------------------------------------------------------------------
#define BATCH     2
#define SEQ       2048
#define DMODEL    4096
#define NHEADS    32
#define KVHEADS   8
#define HEADDIM   128
#define QKV_N     (DMODEL + 2 * KVHEADS * HEADDIM)   // 6144
#define TOKENS    (BATCH * SEQ)                      // 4096
#define CLIP_V    8.0f
#define INV_SQRT_D 0.08838834764831845f

// ---------------------------------------------------------------------------
// Scratch (device globals; no dynamic allocation allowed)
// ---------------------------------------------------------------------------
__device__ float g_qkv  [(size_t)TOKENS * QKV_N];
__device__ float g_q    [(size_t)BATCH * NHEADS  * SEQ * HEADDIM];
__device__ float g_k    [(size_t)BATCH * KVHEADS * SEQ * HEADDIM];
__device__ float g_vt   [(size_t)BATCH * KVHEADS * HEADDIM * SEQ];
__device__ float g_attn [(size_t)TOKENS * DMODEL];
__device__ float g_hid_r[(size_t)TOKENS * DMODEL];
__device__ float g_wq_r [(size_t)QKV_N  * DMODEL];
__device__ float g_wo_r [(size_t)DMODEL * DMODEL];

// ---------------------------------------------------------------------------
// helpers
// ---------------------------------------------------------------------------
__device__ __forceinline__ uint32_t f2tf(float x) {
    uint32_t r;
    asm("cvt.rna.tf32.f32 %0, %1;" : "=r"(r) : "f"(x));
    return r;
}
__device__ __forceinline__ float tfr(float x) { return __uint_as_float(f2tf(x)); }
__device__ __forceinline__ void mma_tf32(float* c, const uint32_t* a, const uint32_t* b) {
    asm volatile(
        "mma.sync.aligned.m16n8k8.row.col.f32.tf32.tf32.f32 "
        "{%0,%1,%2,%3}, {%4,%5,%6,%7}, {%8,%9}, {%0,%1,%2,%3};"
        : "+f"(c[0]), "+f"(c[1]), "+f"(c[2]), "+f"(c[3])
        : "r"(a[0]), "r"(a[1]), "r"(a[2]), "r"(a[3]), "r"(b[0]), "r"(b[1]));
}
__device__ __forceinline__ void cp16(uint32_t s, const void* g) {
    asm volatile("cp.async.cg.shared.global [%0], [%1], 16;" :: "r"(s), "l"(g));
}
// ldmatrix x4: four 8x8 b16 matrices == four 8x4 tf32 blocks.
// Lane->element distribution matches m16n8k8.tf32 fragment layout exactly.
__device__ __forceinline__ void ldsm_x4(uint32_t* r, uint32_t addr) {
    asm volatile("ldmatrix.sync.aligned.m8n8.x4.shared.b16 {%0,%1,%2,%3}, [%4];"
                 : "=r"(r[0]), "=r"(r[1]), "=r"(r[2]), "=r"(r[3]) : "r"(addr));
}

// ---------------------------------------------------------------------------
// elementwise tf32 pre-round (float4 grid-stride)
// ---------------------------------------------------------------------------
__global__ __launch_bounds__(256)
void round_tf32_kernel(const float4* __restrict__ in, float4* __restrict__ out, int n4)
{
    for (int i = blockIdx.x * blockDim.x + threadIdx.x; i < n4; i += gridDim.x * blockDim.x) {
        float4 v = in[i];
        v.x = tfr(v.x); v.y = tfr(v.y); v.z = tfr(v.z); v.w = tfr(v.w);
        out[i] = v;
    }
}

// ---------------------------------------------------------------------------
// TF32 tensor-core GEMM:  C[M,N] = A[M,K] * B[N,K]^T  (operands pre-rounded)
// 128x128x32 block tile, 8 warps (2x4), warp tile 64x32, 3-stage cp.async.
// Fragment feeding via ldmatrix (pitch 36 -> conflict-free).
// ---------------------------------------------------------------------------
#define BM 128
#define BN 128
#define BKg 32
#define BKP 36
#define STAGES 3
#define STAGE_FLOATS (BM * BKP + BN * BKP)
#define GEMM_SMEM_BYTES (STAGES * STAGE_FLOATS * 4)

template <bool DO_CLIP>
__global__ __launch_bounds__(256)
void gemm_tf32(const float* __restrict__ A, const float* __restrict__ B,
               float* __restrict__ C, int M, int N, int K)
{
    extern __shared__ float sm[];
    const uint32_t smem_base = (uint32_t)__cvta_generic_to_shared(sm);

    const int tid = threadIdx.x;
    const int ln  = tid & 31;
    const int wid = tid >> 5;
    const int wm  = wid >> 2;
    const int wn  = wid & 3;
    const int m0  = blockIdx.y * BM;
    const int n0  = blockIdx.x * BN;
    const int lq  = ln >> 2;
    const int lr  = ln & 3;

    // per-lane ldmatrix offsets (bytes, relative to stage A/B base)
    const uint32_t a_lane = (uint32_t)(((wm * 64 + (ln & 15)) * BKP + (ln >> 4) * 4) * 4);
    const uint32_t b_lane = (uint32_t)(((wn * 32 + (ln >> 4) * 8 + (ln & 7)) * BKP
                                        + ((ln >> 3) & 1) * 4) * 4);

    const float* Abase = A + (size_t)m0 * K;
    const float* Bbase = B + (size_t)n0 * K;

    auto load_stage = [&](int kt, int s) {
        const float* Ag = Abase + kt * BKg;
        const float* Bg = Bbase + kt * BKg;
        const uint32_t sa = smem_base + (uint32_t)(s * STAGE_FLOATS) * 4u;
        const uint32_t sb = sa + BM * BKP * 4u;
        #pragma unroll
        for (int r = 0; r < 4; r++) {
            const int i   = r * 256 + tid;
            const int row = i >> 3;
            const int kc  = (i & 7) << 2;
            cp16(sa + (uint32_t)(row * BKP + kc) * 4u, Ag + (size_t)row * K + kc);
            cp16(sb + (uint32_t)(row * BKP + kc) * 4u, Bg + (size_t)row * K + kc);
        }
        asm volatile("cp.async.commit_group;");
    };

    #pragma unroll
    for (int s = 0; s < STAGES - 1; s++) load_stage(s, s);

    float acc[4][4][4];
    #pragma unroll
    for (int a = 0; a < 4; a++)
        #pragma unroll
        for (int b = 0; b < 4; b++)
            #pragma unroll
            for (int c = 0; c < 4; c++) acc[a][b][c] = 0.0f;

    const int nk = K / BKg;
    for (int kt = 0; kt < nk; kt++) {
        if (kt + STAGES - 1 < nk) load_stage(kt + STAGES - 1, (kt + STAGES - 1) % STAGES);
        else asm volatile("cp.async.commit_group;");
        asm volatile("cp.async.wait_group %0;" :: "n"(STAGES - 1));
        __syncthreads();

        const uint32_t as_s = smem_base + (uint32_t)((kt % STAGES) * STAGE_FLOATS) * 4u;
        const uint32_t bs_s = as_s + BM * BKP * 4u;
        const uint32_t aa = as_s + a_lane;
        const uint32_t bb = bs_s + b_lane;

        #pragma unroll
        for (int ks = 0; ks < 4; ks++) {
            const uint32_t k0b = (uint32_t)(ks * 8 * 4);
            uint32_t af[4][4], bf[2][4];
            #pragma unroll
            for (int mt = 0; mt < 4; mt++)
                ldsm_x4(af[mt], aa + (uint32_t)(mt * 16 * BKP * 4) + k0b);
            ldsm_x4(bf[0], bb + k0b);                                  // nt 0,1
            ldsm_x4(bf[1], bb + (uint32_t)(16 * BKP * 4) + k0b);       // nt 2,3
            #pragma unroll
            for (int mt = 0; mt < 4; mt++) {
                mma_tf32(acc[mt][0], af[mt], &bf[0][0]);
                mma_tf32(acc[mt][1], af[mt], &bf[0][2]);
                mma_tf32(acc[mt][2], af[mt], &bf[1][0]);
                mma_tf32(acc[mt][3], af[mt], &bf[1][2]);
            }
        }
        __syncthreads();
    }

    float* Cg = C + (size_t)(m0 + wm * 64) * N + n0 + wn * 32;
    #pragma unroll
    for (int mt = 0; mt < 4; mt++) {
        #pragma unroll
        for (int nt = 0; nt < 4; nt++) {
            const int row = mt * 16 + lq;
            const int col = nt * 8 + lr * 2;
            float2 v0 = make_float2(acc[mt][nt][0], acc[mt][nt][1]);
            float2 v1 = make_float2(acc[mt][nt][2], acc[mt][nt][3]);
            if (DO_CLIP) {
                v0.x = fminf(fmaxf(v0.x, -CLIP_V), CLIP_V);
                v0.y = fminf(fmaxf(v0.y, -CLIP_V), CLIP_V);
                v1.x = fminf(fmaxf(v1.x, -CLIP_V), CLIP_V);
                v1.y = fminf(fmaxf(v1.y, -CLIP_V), CLIP_V);
            }
            *(float2*)(Cg + (size_t)row * N + col)       = v0;
            *(float2*)(Cg + (size_t)(row + 8) * N + col) = v1;
        }
    }
}

// ---------------------------------------------------------------------------
// RoPE + layout (unchanged from R3)
// ---------------------------------------------------------------------------
__global__ __launch_bounds__(256)
void rope_kernel()
{
    const int token = blockIdx.x;
    const int b    = token / SEQ;
    const int spos = token - b * SEQ;
    const float* row = g_qkv + (size_t)token * QKV_N;
    const float posf = (float)spos;

    for (int idx = threadIdx.x; idx < (NHEADS + KVHEADS) * 64; idx += 256) {
        const int h = idx >> 6;
        const int j = idx & 63;
        const float freq = powf(500000.0f, -(float)j * (1.0f / 64.0f));
        float s, c;
        sincosf(posf * freq, &s, &c);

        const float x1 = row[h * HEADDIM + j];
        const float x2 = row[h * HEADDIM + 64 + j];
        const float y1 = x1 * c - x2 * s;
        const float y2 = x2 * c + x1 * s;

        if (h < NHEADS) {
            float* q = g_q + ((size_t)(b * NHEADS + h) * SEQ + spos) * HEADDIM;
            q[j]      = tfr(y1 * INV_SQRT_D);
            q[j + 64] = tfr(y2 * INV_SQRT_D);
        } else {
            float* k = g_k + ((size_t)(b * KVHEADS + (h - NHEADS)) * SEQ + spos) * HEADDIM;
            k[j]      = tfr(y1);
            k[j + 64] = tfr(y2);
        }
    }

    const float* vrow = row + DMODEL + KVHEADS * HEADDIM;
    for (int idx = threadIdx.x; idx < KVHEADS * HEADDIM; idx += 256) {
        const int hk = idx >> 7;
        const int d  = idx & 127;
        g_vt[((size_t)(b * KVHEADS + hk) * HEADDIM + d) * SEQ + spos] = tfr(vrow[hk * HEADDIM + d]);
    }
}

// ---------------------------------------------------------------------------
// Tensor-core causal flash attention (tf32 mma, ldmatrix feeding).
// CTA: 64 q-rows x (head,batch). 4 warps, each owns 16 q-rows.
// smem: Qs[64][132], KP[64][132] (K tile, reused for P), Vt[128][68].
// ---------------------------------------------------------------------------
#define QK_PITCH 132
#define V_PITCH  68
#define ATTN_SMEM_FLOATS (2 * 64 * QK_PITCH + 128 * V_PITCH)
#define ATTN_SMEM_BYTES  (ATTN_SMEM_FLOATS * 4)

__global__ __launch_bounds__(128, 2)
void attn_kernel()
{
    extern __shared__ float sm[];
    float* KP = sm + 64 * QK_PITCH;
    const uint32_t smem_base = (uint32_t)__cvta_generic_to_shared(sm);
    const uint32_t kp_base   = smem_base + 64 * QK_PITCH * 4u;
    const uint32_t vt_base   = smem_base + 2 * 64 * QK_PITCH * 4u;

    const int qt = blockIdx.x;
    const int h  = blockIdx.y;
    const int b  = blockIdx.z;
    const int hk = h >> 2;
    const int q0 = qt * 64;

    const int tid = threadIdx.x;
    const int ln  = tid & 31;
    const int wid = tid >> 5;
    const int lq  = ln >> 2;
    const int lr  = ln & 3;

    // ldmatrix per-lane offsets (bytes)
    const uint32_t a_lane_qk = (uint32_t)(((wid * 16 + (ln & 15)) * QK_PITCH
                                           + (ln >> 4) * 4) * 4);
    const uint32_t b_lane_qk = (uint32_t)((((ln >> 4) * 8 + (ln & 7)) * QK_PITCH
                                           + ((ln >> 3) & 1) * 4) * 4);
    const uint32_t b_lane_v  = (uint32_t)((((ln >> 4) * 8 + (ln & 7)) * V_PITCH
                                           + ((ln >> 3) & 1) * 4) * 4);

    const float* Qg = g_q  + ((size_t)(b * NHEADS  + h)  * SEQ + q0) * HEADDIM;
    const float* Kg = g_k  + ((size_t)(b * KVHEADS + hk) * SEQ) * HEADDIM;
    const float* Vg = g_vt + ((size_t)(b * KVHEADS + hk) * HEADDIM) * SEQ;

    for (int i = tid; i < 2048; i += 128) {
        const int r  = i >> 5;
        const int c4 = (i & 31) << 2;
        cp16(smem_base + (uint32_t)(r * QK_PITCH + c4) * 4u, Qg + (size_t)r * HEADDIM + c4);
    }
    asm volatile("cp.async.commit_group;");

    float m0 = -3.0e38f, m1 = -3.0e38f, l0 = 0.0f, l1 = 0.0f;
    float o[16][4];
    #pragma unroll
    for (int nt = 0; nt < 16; nt++)
        #pragma unroll
        for (int c = 0; c < 4; c++) o[nt][c] = 0.0f;

    for (int jt = 0; jt <= qt; jt++) {
        const int j0 = jt * 64;
        __syncthreads();

        for (int i = tid; i < 2048; i += 128) {
            const int r  = i >> 5;
            const int c4 = (i & 31) << 2;
            cp16(kp_base + (uint32_t)(r * QK_PITCH + c4) * 4u,
                 Kg + (size_t)(j0 + r) * HEADDIM + c4);
        }
        for (int i = tid; i < 2048; i += 128) {
            const int r  = i >> 4;
            const int c4 = (i & 15) << 2;
            cp16(vt_base + (uint32_t)(r * V_PITCH + c4) * 4u,
                 Vg + (size_t)r * SEQ + j0 + c4);
        }
        asm volatile("cp.async.commit_group;");
        asm volatile("cp.async.wait_group 0;");
        __syncthreads();

        // ---- S = Q K^T : ldmatrix feeding ----
        float s_[8][4];
        #pragma unroll
        for (int t = 0; t < 8; t++)
            #pragma unroll
            for (int c = 0; c < 4; c++) s_[t][c] = 0.0f;

        #pragma unroll
        for (int k0 = 0; k0 < 128; k0 += 8) {
            const uint32_t k0b = (uint32_t)(k0 * 4);
            uint32_t a[4];
            ldsm_x4(a, smem_base + a_lane_qk + k0b);
            #pragma unroll
            for (int p = 0; p < 4; p++) {
                uint32_t bt[4];
                ldsm_x4(bt, kp_base + b_lane_qk + (uint32_t)(p * 16 * QK_PITCH * 4) + k0b);
                mma_tf32(s_[2 * p],     a, &bt[0]);
                mma_tf32(s_[2 * p + 1], a, &bt[2]);
            }
        }

        if (jt == qt) {
            const int r0 = wid * 16 + lq;
            #pragma unroll
            for (int t = 0; t < 8; t++) {
                const int c0 = t * 8 + 2 * lr;
                if (c0     > r0)     s_[t][0] = -3.0e38f;
                if (c0 + 1 > r0)     s_[t][1] = -3.0e38f;
                if (c0     > r0 + 8) s_[t][2] = -3.0e38f;
                if (c0 + 1 > r0 + 8) s_[t][3] = -3.0e38f;
            }
        }

        // ---- online softmax ----
        float mx0 = -3.0e38f, mx1 = -3.0e38f;
        #pragma unroll
        for (int t = 0; t < 8; t++) {
            mx0 = fmaxf(mx0, fmaxf(s_[t][0], s_[t][1]));
            mx1 = fmaxf(mx1, fmaxf(s_[t][2], s_[t][3]));
        }
        mx0 = fmaxf(mx0, __shfl_xor_sync(0xffffffffu, mx0, 1));
        mx0 = fmaxf(mx0, __shfl_xor_sync(0xffffffffu, mx0, 2));
        mx1 = fmaxf(mx1, __shfl_xor_sync(0xffffffffu, mx1, 1));
        mx1 = fmaxf(mx1, __shfl_xor_sync(0xffffffffu, mx1, 2));

        const float mn0 = fmaxf(m0, mx0);
        const float mn1 = fmaxf(m1, mx1);
        const float al0 = __expf(m0 - mn0);
        const float al1 = __expf(m1 - mn1);
        float rs0 = 0.0f, rs1 = 0.0f;
        #pragma unroll
        for (int t = 0; t < 8; t++) {
            s_[t][0] = __expf(s_[t][0] - mn0); rs0 += s_[t][0];
            s_[t][1] = __expf(s_[t][1] - mn0); rs0 += s_[t][1];
            s_[t][2] = __expf(s_[t][2] - mn1); rs1 += s_[t][2];
            s_[t][3] = __expf(s_[t][3] - mn1); rs1 += s_[t][3];
        }
        rs0 += __shfl_xor_sync(0xffffffffu, rs0, 1);
        rs0 += __shfl_xor_sync(0xffffffffu, rs0, 2);
        rs1 += __shfl_xor_sync(0xffffffffu, rs1, 1);
        rs1 += __shfl_xor_sync(0xffffffffu, rs1, 2);
        l0 = l0 * al0 + rs0;  m0 = mn0;
        l1 = l1 * al1 + rs1;  m1 = mn1;
        #pragma unroll
        for (int nt = 0; nt < 16; nt++) {
            o[nt][0] *= al0; o[nt][1] *= al0;
            o[nt][2] *= al1; o[nt][3] *= al1;
        }

        __syncthreads();   // all warps done reading K from KP

        // ---- store P (tf32-rounded) into KP as [m][j] ----
        {
            float* p0 = KP + (wid * 16 + lq) * QK_PITCH + 2 * lr;
            float* p1 = p0 + 8 * QK_PITCH;
            #pragma unroll
            for (int t = 0; t < 8; t++) {
                p0[t * 8]     = tfr(s_[t][0]);
                p0[t * 8 + 1] = tfr(s_[t][1]);
                p1[t * 8]     = tfr(s_[t][2]);
                p1[t * 8 + 1] = tfr(s_[t][3]);
            }
        }
        __syncthreads();

        // ---- O += P Vt : ldmatrix feeding ----
        #pragma unroll
        for (int k0 = 0; k0 < 64; k0 += 8) {
            const uint32_t k0b = (uint32_t)(k0 * 4);
            uint32_t a[4];
            ldsm_x4(a, kp_base + a_lane_qk + k0b);
            #pragma unroll
            for (int p = 0; p < 8; p++) {
                uint32_t bt[4];
                ldsm_x4(bt, vt_base + b_lane_v + (uint32_t)(p * 16 * V_PITCH * 4) + k0b);
                mma_tf32(o[2 * p],     a, &bt[0]);
                mma_tf32(o[2 * p + 1], a, &bt[2]);
            }
        }
    }

    // ---- epilogue ----
    const float inv0 = 1.0f / l0;
    const float inv1 = 1.0f / l1;
    const int s0 = q0 + wid * 16 + lq;
    float* O0 = g_attn + (size_t)(b * SEQ + s0) * DMODEL + h * HEADDIM + 2 * lr;
    float* O1 = O0 + (size_t)8 * DMODEL;
    #pragma unroll
    for (int nt = 0; nt < 16; nt++) {
        float2 v0 = make_float2(tfr(o[nt][0] * inv0), tfr(o[nt][1] * inv0));
        float2 v1 = make_float2(tfr(o[nt][2] * inv1), tfr(o[nt][3] * inv1));
        *(float2*)(O0 + nt * 8) = v0;
        *(float2*)(O1 + nt * 8) = v1;
    }
}

// ---------------------------------------------------------------------------
// Launch sequence
// Inputs: 0=hidden_states f32, 1=position_ids i64 (arange), 2=attention_mask
//         (causal), 3=Wqkv_w f32, 4=out_w f32
// ---------------------------------------------------------------------------
extern "C" void kernel_launch(void* const* d_in, const int* in_sizes, int n_in,
                              void* d_out, int out_size)
{
    const float* hidden = (const float*)d_in[0];
    const float* Wqkv   = (const float*)d_in[3];
    const float* out_w  = (const float*)d_in[4];
    float*       out    = (float*)d_out;

    float *qkv_p, *attn_p, *hid_p, *wq_p, *wo_p;
    cudaGetSymbolAddress((void**)&qkv_p,  g_qkv);
    cudaGetSymbolAddress((void**)&attn_p, g_attn);
    cudaGetSymbolAddress((void**)&hid_p,  g_hid_r);
    cudaGetSymbolAddress((void**)&wq_p,   g_wq_r);
    cudaGetSymbolAddress((void**)&wo_p,   g_wo_r);

    cudaFuncSetAttribute(gemm_tf32<true>,
                         cudaFuncAttributeMaxDynamicSharedMemorySize, GEMM_SMEM_BYTES);
    cudaFuncSetAttribute(gemm_tf32<false>,
                         cudaFuncAttributeMaxDynamicSharedMemorySize, GEMM_SMEM_BYTES);
    cudaFuncSetAttribute(attn_kernel,
                         cudaFuncAttributeMaxDynamicSharedMemorySize, ATTN_SMEM_BYTES);

    // 0) pre-round operands to tf32
    round_tf32_kernel<<<1184, 256>>>((const float4*)hidden, (float4*)hid_p,
                                     TOKENS * DMODEL / 4);
    round_tf32_kernel<<<1184, 256>>>((const float4*)Wqkv, (float4*)wq_p,
                                     QKV_N * DMODEL / 4);
    round_tf32_kernel<<<1184, 256>>>((const float4*)out_w, (float4*)wo_p,
                                     DMODEL * DMODEL / 4);

    // 1) QKV projection with clip
    gemm_tf32<true><<<dim3(QKV_N / BN, TOKENS / BM), 256, GEMM_SMEM_BYTES>>>(
        hid_p, wq_p, qkv_p, TOKENS, QKV_N, DMODEL);

    // 2) RoPE + layouts (tf32-rounded outputs)
    rope_kernel<<<TOKENS, 256>>>();

    // 3) tensor-core causal flash attention
    attn_kernel<<<dim3(SEQ / 64, NHEADS, BATCH), 128, ATTN_SMEM_BYTES>>>();

    // 4) output projection
    gemm_tf32<false><<<dim3(DMODEL / BN, TOKENS / BM), 256, GEMM_SMEM_BYTES>>>(
        attn_p, wo_p, out, TOKENS, DMODEL, DMODEL);
}

// round 7
// speedup vs baseline: 4.2148x; 1.0626x over previous
#include <cuda_runtime.h>
#include <math.h>
#include <stdint.h>

// ---------------------------------------------------------------------------
// Problem constants
// ---------------------------------------------------------------------------
#define BATCH     2
#define SEQ       2048
#define DMODEL    4096
#define NHEADS    32
#define KVHEADS   8
#define HEADDIM   128
#define QKV_N     (DMODEL + 2 * KVHEADS * HEADDIM)   // 6144
#define TOKENS    (BATCH * SEQ)                      // 4096
#define CLIP_V    8.0f
#define INV_SQRT_D 0.08838834764831845f

// ---------------------------------------------------------------------------
// Scratch (device globals; no dynamic allocation allowed)
// ---------------------------------------------------------------------------
__device__ float g_qkv  [(size_t)TOKENS * QKV_N];
__device__ float g_q    [(size_t)BATCH * NHEADS  * SEQ * HEADDIM];
__device__ float g_k    [(size_t)BATCH * KVHEADS * SEQ * HEADDIM];
__device__ float g_vt   [(size_t)BATCH * KVHEADS * HEADDIM * SEQ];
__device__ float g_attn [(size_t)TOKENS * DMODEL];
__device__ float g_hid_r[(size_t)TOKENS * DMODEL];
__device__ float g_wq_r [(size_t)QKV_N  * DMODEL];
__device__ float g_wo_r [(size_t)DMODEL * DMODEL];

// ---------------------------------------------------------------------------
// helpers
// ---------------------------------------------------------------------------
__device__ __forceinline__ uint32_t f2tf(float x) {
    uint32_t r;
    asm("cvt.rna.tf32.f32 %0, %1;" : "=r"(r) : "f"(x));
    return r;
}
__device__ __forceinline__ float tfr(float x) { return __uint_as_float(f2tf(x)); }
__device__ __forceinline__ void mma_tf32(float* c, const uint32_t* a, const uint32_t* b) {
    asm volatile(
        "mma.sync.aligned.m16n8k8.row.col.f32.tf32.tf32.f32 "
        "{%0,%1,%2,%3}, {%4,%5,%6,%7}, {%8,%9}, {%0,%1,%2,%3};"
        : "+f"(c[0]), "+f"(c[1]), "+f"(c[2]), "+f"(c[3])
        : "r"(a[0]), "r"(a[1]), "r"(a[2]), "r"(a[3]), "r"(b[0]), "r"(b[1]));
}
__device__ __forceinline__ void cp16(uint32_t s, const void* g) {
    asm volatile("cp.async.cg.shared.global [%0], [%1], 16;" :: "r"(s), "l"(g));
}
__device__ __forceinline__ void ldsm_x4(uint32_t* r, uint32_t addr) {
    asm volatile("ldmatrix.sync.aligned.m8n8.x4.shared.b16 {%0,%1,%2,%3}, [%4];"
                 : "=r"(r[0]), "=r"(r[1]), "=r"(r[2]), "=r"(r[3]) : "r"(addr));
}

// ---------------------------------------------------------------------------
// elementwise tf32 pre-round (float4 grid-stride)
// ---------------------------------------------------------------------------
__global__ __launch_bounds__(256)
void round_tf32_kernel(const float4* __restrict__ in, float4* __restrict__ out, int n4)
{
    for (int i = blockIdx.x * blockDim.x + threadIdx.x; i < n4; i += gridDim.x * blockDim.x) {
        float4 v = in[i];
        v.x = tfr(v.x); v.y = tfr(v.y); v.z = tfr(v.z); v.w = tfr(v.w);
        out[i] = v;
    }
}

// ---------------------------------------------------------------------------
// TF32 tensor-core GEMM:  C[M,N] = A[M,K] * B[N,K]^T  (operands pre-rounded)
// 128x128x32 block tile, 8 warps (2x4), warp tile 64x32.
// 2-stage cp.async double buffer -> 73.7KB smem -> 2 CTAs/SM.
// ldmatrix fragment feeding (pitch 36 -> conflict-free).
// Epilogue staged through smem (pitch 36: 144B rows, float4-aligned).
// ---------------------------------------------------------------------------
#define BM 128
#define BN 128
#define BKg 32
#define BKP 36
#define STAGES 2
#define STAGE_FLOATS (BM * BKP + BN * BKP)            // 9216
#define GEMM_SMEM_BYTES (STAGES * STAGE_FLOATS * 4)   // 73,728
#define EP_PITCH 36                                   // 144B: 16B-aligned rows

template <bool DO_CLIP>
__global__ __launch_bounds__(256, 2)
void gemm_tf32(const float* __restrict__ A, const float* __restrict__ B,
               float* __restrict__ C, int M, int N, int K)
{
    extern __shared__ float sm[];
    const uint32_t smem_base = (uint32_t)__cvta_generic_to_shared(sm);

    const int tid = threadIdx.x;
    const int ln  = tid & 31;
    const int wid = tid >> 5;
    const int wm  = wid >> 2;
    const int wn  = wid & 3;
    const int m0  = blockIdx.y * BM;
    const int n0  = blockIdx.x * BN;
    const int lq  = ln >> 2;
    const int lr  = ln & 3;

    const uint32_t a_lane = (uint32_t)(((wm * 64 + (ln & 15)) * BKP + (ln >> 4) * 4) * 4);
    const uint32_t b_lane = (uint32_t)(((wn * 32 + (ln >> 4) * 8 + (ln & 7)) * BKP
                                        + ((ln >> 3) & 1) * 4) * 4);

    const float* Abase = A + (size_t)m0 * K;
    const float* Bbase = B + (size_t)n0 * K;

    auto load_stage = [&](int kt, int s) {
        const float* Ag = Abase + kt * BKg;
        const float* Bg = Bbase + kt * BKg;
        const uint32_t sa = smem_base + (uint32_t)(s * STAGE_FLOATS) * 4u;
        const uint32_t sb = sa + BM * BKP * 4u;
        #pragma unroll
        for (int r = 0; r < 4; r++) {
            const int i   = r * 256 + tid;
            const int row = i >> 3;
            const int kc  = (i & 7) << 2;
            cp16(sa + (uint32_t)(row * BKP + kc) * 4u, Ag + (size_t)row * K + kc);
            cp16(sb + (uint32_t)(row * BKP + kc) * 4u, Bg + (size_t)row * K + kc);
        }
        asm volatile("cp.async.commit_group;");
    };

    load_stage(0, 0);

    float acc[4][4][4];
    #pragma unroll
    for (int a = 0; a < 4; a++)
        #pragma unroll
        for (int b = 0; b < 4; b++)
            #pragma unroll
            for (int c = 0; c < 4; c++) acc[a][b][c] = 0.0f;

    const int nk = K / BKg;
    for (int kt = 0; kt < nk; kt++) {
        if (kt + 1 < nk) {
            load_stage(kt + 1, (kt + 1) & 1);
            asm volatile("cp.async.wait_group 1;");
        } else {
            asm volatile("cp.async.wait_group 0;");
        }
        __syncthreads();

        const uint32_t as_s = smem_base + (uint32_t)((kt & 1) * STAGE_FLOATS) * 4u;
        const uint32_t aa = as_s + a_lane;
        const uint32_t bb = as_s + BM * BKP * 4u + b_lane;

        #pragma unroll
        for (int ks = 0; ks < 4; ks++) {
            const uint32_t k0b = (uint32_t)(ks * 8 * 4);
            uint32_t af[4][4], bf[2][4];
            #pragma unroll
            for (int mt = 0; mt < 4; mt++)
                ldsm_x4(af[mt], aa + (uint32_t)(mt * 16 * BKP * 4) + k0b);
            ldsm_x4(bf[0], bb + k0b);
            ldsm_x4(bf[1], bb + (uint32_t)(16 * BKP * 4) + k0b);
            #pragma unroll
            for (int mt = 0; mt < 4; mt++) {
                mma_tf32(acc[mt][0], af[mt], &bf[0][0]);
                mma_tf32(acc[mt][1], af[mt], &bf[0][2]);
                mma_tf32(acc[mt][2], af[mt], &bf[1][0]);
                mma_tf32(acc[mt][3], af[mt], &bf[1][2]);
            }
        }
        __syncthreads();
    }

    // --- epilogue via smem (pitch 36 floats = 144B: every row float4-aligned).
    //     Each warp stages its 64x32 tile 16 rows at a time, then emits
    //     coalesced float4 stores (8 lanes x 32 floats per row-group).
    float* ep = sm + wid * (64 * EP_PITCH);
    #pragma unroll
    for (int mt = 0; mt < 4; mt++) {
        __syncwarp();
        #pragma unroll
        for (int nt = 0; nt < 4; nt++) {
            float* p0 = ep + (lq)     * EP_PITCH + nt * 8 + lr * 2;
            float* p1 = ep + (lq + 8) * EP_PITCH + nt * 8 + lr * 2;
            p0[0] = acc[mt][nt][0]; p0[1] = acc[mt][nt][1];
            p1[0] = acc[mt][nt][2]; p1[1] = acc[mt][nt][3];
        }
        __syncwarp();
        #pragma unroll
        for (int rr = 0; rr < 4; rr++) {
            const int row = rr * 4 + (ln >> 3);      // 0..15
            const int c4  = (ln & 7) * 4;            // 0..28
            float4 v = *(float4*)&ep[row * EP_PITCH + c4];
            if (DO_CLIP) {
                v.x = fminf(fmaxf(v.x, -CLIP_V), CLIP_V);
                v.y = fminf(fmaxf(v.y, -CLIP_V), CLIP_V);
                v.z = fminf(fmaxf(v.z, -CLIP_V), CLIP_V);
                v.w = fminf(fmaxf(v.w, -CLIP_V), CLIP_V);
            }
            *(float4*)(C + (size_t)(m0 + wm * 64 + mt * 16 + row) * N
                         + n0 + wn * 32 + c4) = v;
        }
    }
}

// ---------------------------------------------------------------------------
// RoPE + layout
// ---------------------------------------------------------------------------
__global__ __launch_bounds__(256)
void rope_kernel()
{
    const int token = blockIdx.x;
    const int b    = token / SEQ;
    const int spos = token - b * SEQ;
    const float* row = g_qkv + (size_t)token * QKV_N;
    const float posf = (float)spos;

    for (int idx = threadIdx.x; idx < (NHEADS + KVHEADS) * 64; idx += 256) {
        const int h = idx >> 6;
        const int j = idx & 63;
        const float freq = __powf(500000.0f, -(float)j * (1.0f / 64.0f));
        float s, c;
        sincosf(posf * freq, &s, &c);

        const float x1 = row[h * HEADDIM + j];
        const float x2 = row[h * HEADDIM + 64 + j];
        const float y1 = x1 * c - x2 * s;
        const float y2 = x2 * c + x1 * s;

        if (h < NHEADS) {
            float* q = g_q + ((size_t)(b * NHEADS + h) * SEQ + spos) * HEADDIM;
            q[j]      = tfr(y1 * INV_SQRT_D);
            q[j + 64] = tfr(y2 * INV_SQRT_D);
        } else {
            float* k = g_k + ((size_t)(b * KVHEADS + (h - NHEADS)) * SEQ + spos) * HEADDIM;
            k[j]      = tfr(y1);
            k[j + 64] = tfr(y2);
        }
    }

    const float* vrow = row + DMODEL + KVHEADS * HEADDIM;
    for (int idx = threadIdx.x; idx < KVHEADS * HEADDIM; idx += 256) {
        const int hk = idx >> 7;
        const int d  = idx & 127;
        g_vt[((size_t)(b * KVHEADS + hk) * HEADDIM + d) * SEQ + spos] = tfr(vrow[hk * HEADDIM + d]);
    }
}

// ---------------------------------------------------------------------------
// Tensor-core causal flash attention (tf32 mma, ldmatrix feeding).
// ---------------------------------------------------------------------------
#define QK_PITCH 132
#define V_PITCH  68
#define ATTN_SMEM_FLOATS (2 * 64 * QK_PITCH + 128 * V_PITCH)
#define ATTN_SMEM_BYTES  (ATTN_SMEM_FLOATS * 4)

__global__ __launch_bounds__(128, 2)
void attn_kernel()
{
    extern __shared__ float sm[];
    float* KP = sm + 64 * QK_PITCH;
    const uint32_t smem_base = (uint32_t)__cvta_generic_to_shared(sm);
    const uint32_t kp_base   = smem_base + 64 * QK_PITCH * 4u;
    const uint32_t vt_base   = smem_base + 2 * 64 * QK_PITCH * 4u;

    const int qt = blockIdx.x;
    const int h  = blockIdx.y;
    const int b  = blockIdx.z;
    const int hk = h >> 2;
    const int q0 = qt * 64;

    const int tid = threadIdx.x;
    const int ln  = tid & 31;
    const int wid = tid >> 5;
    const int lq  = ln >> 2;
    const int lr  = ln & 3;

    const uint32_t a_lane_qk = (uint32_t)(((wid * 16 + (ln & 15)) * QK_PITCH
                                           + (ln >> 4) * 4) * 4);
    const uint32_t b_lane_qk = (uint32_t)((((ln >> 4) * 8 + (ln & 7)) * QK_PITCH
                                           + ((ln >> 3) & 1) * 4) * 4);
    const uint32_t b_lane_v  = (uint32_t)((((ln >> 4) * 8 + (ln & 7)) * V_PITCH
                                           + ((ln >> 3) & 1) * 4) * 4);

    const float* Qg = g_q  + ((size_t)(b * NHEADS  + h)  * SEQ + q0) * HEADDIM;
    const float* Kg = g_k  + ((size_t)(b * KVHEADS + hk) * SEQ) * HEADDIM;
    const float* Vg = g_vt + ((size_t)(b * KVHEADS + hk) * HEADDIM) * SEQ;

    for (int i = tid; i < 2048; i += 128) {
        const int r  = i >> 5;
        const int c4 = (i & 31) << 2;
        cp16(smem_base + (uint32_t)(r * QK_PITCH + c4) * 4u, Qg + (size_t)r * HEADDIM + c4);
    }
    asm volatile("cp.async.commit_group;");

    float m0 = -3.0e38f, m1 = -3.0e38f, l0 = 0.0f, l1 = 0.0f;
    float o[16][4];
    #pragma unroll
    for (int nt = 0; nt < 16; nt++)
        #pragma unroll
        for (int c = 0; c < 4; c++) o[nt][c] = 0.0f;

    for (int jt = 0; jt <= qt; jt++) {
        const int j0 = jt * 64;
        __syncthreads();

        for (int i = tid; i < 2048; i += 128) {
            const int r  = i >> 5;
            const int c4 = (i & 31) << 2;
            cp16(kp_base + (uint32_t)(r * QK_PITCH + c4) * 4u,
                 Kg + (size_t)(j0 + r) * HEADDIM + c4);
        }
        for (int i = tid; i < 2048; i += 128) {
            const int r  = i >> 4;
            const int c4 = (i & 15) << 2;
            cp16(vt_base + (uint32_t)(r * V_PITCH + c4) * 4u,
                 Vg + (size_t)r * SEQ + j0 + c4);
        }
        asm volatile("cp.async.commit_group;");
        asm volatile("cp.async.wait_group 0;");
        __syncthreads();

        float s_[8][4];
        #pragma unroll
        for (int t = 0; t < 8; t++)
            #pragma unroll
            for (int c = 0; c < 4; c++) s_[t][c] = 0.0f;

        #pragma unroll
        for (int k0 = 0; k0 < 128; k0 += 8) {
            const uint32_t k0b = (uint32_t)(k0 * 4);
            uint32_t a[4];
            ldsm_x4(a, smem_base + a_lane_qk + k0b);
            #pragma unroll
            for (int p = 0; p < 4; p++) {
                uint32_t bt[4];
                ldsm_x4(bt, kp_base + b_lane_qk + (uint32_t)(p * 16 * QK_PITCH * 4) + k0b);
                mma_tf32(s_[2 * p],     a, &bt[0]);
                mma_tf32(s_[2 * p + 1], a, &bt[2]);
            }
        }

        if (jt == qt) {
            const int r0 = wid * 16 + lq;
            #pragma unroll
            for (int t = 0; t < 8; t++) {
                const int c0 = t * 8 + 2 * lr;
                if (c0     > r0)     s_[t][0] = -3.0e38f;
                if (c0 + 1 > r0)     s_[t][1] = -3.0e38f;
                if (c0     > r0 + 8) s_[t][2] = -3.0e38f;
                if (c0 + 1 > r0 + 8) s_[t][3] = -3.0e38f;
            }
        }

        float mx0 = -3.0e38f, mx1 = -3.0e38f;
        #pragma unroll
        for (int t = 0; t < 8; t++) {
            mx0 = fmaxf(mx0, fmaxf(s_[t][0], s_[t][1]));
            mx1 = fmaxf(mx1, fmaxf(s_[t][2], s_[t][3]));
        }
        mx0 = fmaxf(mx0, __shfl_xor_sync(0xffffffffu, mx0, 1));
        mx0 = fmaxf(mx0, __shfl_xor_sync(0xffffffffu, mx0, 2));
        mx1 = fmaxf(mx1, __shfl_xor_sync(0xffffffffu, mx1, 1));
        mx1 = fmaxf(mx1, __shfl_xor_sync(0xffffffffu, mx1, 2));

        const float mn0 = fmaxf(m0, mx0);
        const float mn1 = fmaxf(m1, mx1);
        const float al0 = __expf(m0 - mn0);
        const float al1 = __expf(m1 - mn1);
        float rs0 = 0.0f, rs1 = 0.0f;
        #pragma unroll
        for (int t = 0; t < 8; t++) {
            s_[t][0] = __expf(s_[t][0] - mn0); rs0 += s_[t][0];
            s_[t][1] = __expf(s_[t][1] - mn0); rs0 += s_[t][1];
            s_[t][2] = __expf(s_[t][2] - mn1); rs1 += s_[t][2];
            s_[t][3] = __expf(s_[t][3] - mn1); rs1 += s_[t][3];
        }
        rs0 += __shfl_xor_sync(0xffffffffu, rs0, 1);
        rs0 += __shfl_xor_sync(0xffffffffu, rs0, 2);
        rs1 += __shfl_xor_sync(0xffffffffu, rs1, 1);
        rs1 += __shfl_xor_sync(0xffffffffu, rs1, 2);
        l0 = l0 * al0 + rs0;  m0 = mn0;
        l1 = l1 * al1 + rs1;  m1 = mn1;
        #pragma unroll
        for (int nt = 0; nt < 16; nt++) {
            o[nt][0] *= al0; o[nt][1] *= al0;
            o[nt][2] *= al1; o[nt][3] *= al1;
        }

        __syncthreads();

        {
            float* p0 = KP + (wid * 16 + lq) * QK_PITCH + 2 * lr;
            float* p1 = p0 + 8 * QK_PITCH;
            #pragma unroll
            for (int t = 0; t < 8; t++) {
                p0[t * 8]     = tfr(s_[t][0]);
                p0[t * 8 + 1] = tfr(s_[t][1]);
                p1[t * 8]     = tfr(s_[t][2]);
                p1[t * 8 + 1] = tfr(s_[t][3]);
            }
        }
        __syncthreads();

        #pragma unroll
        for (int k0 = 0; k0 < 64; k0 += 8) {
            const uint32_t k0b = (uint32_t)(k0 * 4);
            uint32_t a[4];
            ldsm_x4(a, kp_base + a_lane_qk + k0b);
            #pragma unroll
            for (int p = 0; p < 8; p++) {
                uint32_t bt[4];
                ldsm_x4(bt, vt_base + b_lane_v + (uint32_t)(p * 16 * V_PITCH * 4) + k0b);
                mma_tf32(o[2 * p],     a, &bt[0]);
                mma_tf32(o[2 * p + 1], a, &bt[2]);
            }
        }
    }

    const float inv0 = 1.0f / l0;
    const float inv1 = 1.0f / l1;
    const int s0 = q0 + wid * 16 + lq;
    float* O0 = g_attn + (size_t)(b * SEQ + s0) * DMODEL + h * HEADDIM + 2 * lr;
    float* O1 = O0 + (size_t)8 * DMODEL;
    #pragma unroll
    for (int nt = 0; nt < 16; nt++) {
        float2 v0 = make_float2(tfr(o[nt][0] * inv0), tfr(o[nt][1] * inv0));
        float2 v1 = make_float2(tfr(o[nt][2] * inv1), tfr(o[nt][3] * inv1));
        *(float2*)(O0 + nt * 8) = v0;
        *(float2*)(O1 + nt * 8) = v1;
    }
}

// ---------------------------------------------------------------------------
// Launch sequence
// ---------------------------------------------------------------------------
extern "C" void kernel_launch(void* const* d_in, const int* in_sizes, int n_in,
                              void* d_out, int out_size)
{
    const float* hidden = (const float*)d_in[0];
    const float* Wqkv   = (const float*)d_in[3];
    const float* out_w  = (const float*)d_in[4];
    float*       out    = (float*)d_out;

    float *qkv_p, *attn_p, *hid_p, *wq_p, *wo_p;
    cudaGetSymbolAddress((void**)&qkv_p,  g_qkv);
    cudaGetSymbolAddress((void**)&attn_p, g_attn);
    cudaGetSymbolAddress((void**)&hid_p,  g_hid_r);
    cudaGetSymbolAddress((void**)&wq_p,   g_wq_r);
    cudaGetSymbolAddress((void**)&wo_p,   g_wo_r);

    cudaFuncSetAttribute(gemm_tf32<true>,
                         cudaFuncAttributeMaxDynamicSharedMemorySize, GEMM_SMEM_BYTES);
    cudaFuncSetAttribute(gemm_tf32<false>,
                         cudaFuncAttributeMaxDynamicSharedMemorySize, GEMM_SMEM_BYTES);
    cudaFuncSetAttribute(attn_kernel,
                         cudaFuncAttributeMaxDynamicSharedMemorySize, ATTN_SMEM_BYTES);

    // 0) pre-round operands to tf32
    round_tf32_kernel<<<1184, 256>>>((const float4*)hidden, (float4*)hid_p,
                                     TOKENS * DMODEL / 4);
    round_tf32_kernel<<<1184, 256>>>((const float4*)Wqkv, (float4*)wq_p,
                                     QKV_N * DMODEL / 4);
    round_tf32_kernel<<<1184, 256>>>((const float4*)out_w, (float4*)wo_p,
                                     DMODEL * DMODEL / 4);

    // 1) QKV projection with clip
    gemm_tf32<true><<<dim3(QKV_N / BN, TOKENS / BM), 256, GEMM_SMEM_BYTES>>>(
        hid_p, wq_p, qkv_p, TOKENS, QKV_N, DMODEL);

    // 2) RoPE + layouts (tf32-rounded outputs)
    rope_kernel<<<TOKENS, 256>>>();

    // 3) tensor-core causal flash attention
    attn_kernel<<<dim3(SEQ / 64, NHEADS, BATCH), 128, ATTN_SMEM_BYTES>>>();

    // 4) output projection
    gemm_tf32<false><<<dim3(DMODEL / BN, TOKENS / BM), 256, GEMM_SMEM_BYTES>>>(
        attn_p, wo_p, out, TOKENS, DMODEL, DMODEL);
}